// round 1
// baseline (speedup 1.0000x reference)
#include <cuda_runtime.h>

#define EPSV 1e-5f

// ---------------- scratch (device globals; no cudaMalloc allowed) ----------
__device__ float d_F[8 * 1024 * 32];    // f: [b][n=1024][k=32]   (pooled conv1, transposed)
__device__ float d_G[8 * 32 * 4096];    // g: [b][k=32][m=4096]   (conv2)
__device__ float d_HH[8 * 128 * 1024];  // hh:[b][c=128][n=1024]  (pooled conv3)
__device__ float d_O[8 * 128 * 4096];   // o: [b][c=128][m=4096]  (attention out)

// ---------------------------------------------------------------------------
// conv1: 1x1 conv (256->32) + BN + ReLU + 2x2 maxpool  -> d_F[b][n][k]
// grid (32 row-pairs, 8 batches), 256 threads.
// Each thread: 4 oc x (2 cols in row 2r + same 2 cols in row 2r+1) -> 1 pooled col.
// ---------------------------------------------------------------------------
__global__ void __launch_bounds__(256) conv1_kernel(
    const float* __restrict__ x, const float* __restrict__ w,
    const float* __restrict__ cb, const float* __restrict__ cs,
    const float* __restrict__ ct, const float* __restrict__ cm,
    const float* __restrict__ cv)
{
    int b = blockIdx.y;
    int r = blockIdx.x;
    int t = threadIdx.x;
    int og = t >> 5, mg = t & 31;
    int oc0 = og * 4;
    int m0a = mg * 2;

    __shared__ float Xs[32][128];
    __shared__ float Ws[32][32];

    const float* xb = x + (size_t)b * 256 * 4096 + (size_t)r * 128;

    float aa[4][2], ab[4][2];
#pragma unroll
    for (int i = 0; i < 4; i++) { aa[i][0] = aa[i][1] = 0.f; ab[i][0] = ab[i][1] = 0.f; }

    for (int kc = 0; kc < 256; kc += 32) {
        __syncthreads();
        for (int i = t; i < 32 * 128; i += 256) {
            int k = i >> 7, mm = i & 127;
            Xs[k][mm] = xb[(size_t)(kc + k) * 4096 + mm];
        }
        for (int i = t; i < 32 * 32; i += 256) {
            int oc = i >> 5, k = i & 31;
            Ws[k][oc] = w[oc * 256 + kc + k];
        }
        __syncthreads();
#pragma unroll
        for (int k = 0; k < 32; k++) {
            float4 wv = *(const float4*)&Ws[k][oc0];
            float wr[4]; *(float4*)wr = wv;
            float2 xa = *(const float2*)&Xs[k][m0a];
            float2 xb2 = *(const float2*)&Xs[k][m0a + 64];
#pragma unroll
            for (int i = 0; i < 4; i++) {
                aa[i][0] += wr[i] * xa.x;  aa[i][1] += wr[i] * xa.y;
                ab[i][0] += wr[i] * xb2.x; ab[i][1] += wr[i] * xb2.y;
            }
        }
    }
    // BN + ReLU + pool, write f[b][n][oc] with n = r*32 + mg
    float rr[4];
#pragma unroll
    for (int i = 0; i < 4; i++) {
        int oc = oc0 + i;
        float al = cs[oc] * rsqrtf(cv[oc] + EPSV);
        float bc = (cb[oc] - cm[oc]) * al + ct[oc];
        float v0 = fmaxf(aa[i][0] * al + bc, 0.f);
        float v1 = fmaxf(aa[i][1] * al + bc, 0.f);
        float v2 = fmaxf(ab[i][0] * al + bc, 0.f);
        float v3 = fmaxf(ab[i][1] * al + bc, 0.f);
        rr[i] = fmaxf(fmaxf(v0, v1), fmaxf(v2, v3));
    }
    float* fout = d_F + (size_t)b * 32768 + (size_t)(r * 32 + mg) * 32 + oc0;
    *(float4*)fout = *(float4*)rr;
}

// ---------------------------------------------------------------------------
// conv2: 1x1 conv (256->32) + BN + ReLU -> d_G[b][k][m]
// grid (32 m-tiles of 128, 8 batches), 256 threads. 4 oc x 4 m per thread.
// ---------------------------------------------------------------------------
__global__ void __launch_bounds__(256) conv2_kernel(
    const float* __restrict__ x, const float* __restrict__ w,
    const float* __restrict__ cb, const float* __restrict__ cs,
    const float* __restrict__ ct, const float* __restrict__ cm,
    const float* __restrict__ cv)
{
    int b = blockIdx.y;
    int pos0 = blockIdx.x * 128;
    int t = threadIdx.x;
    int og = t >> 5, mg = t & 31;
    int oc0 = og * 4;
    int m0 = mg * 4;

    __shared__ float Xs[32][128];
    __shared__ float Ws[32][32];

    const float* xb = x + (size_t)b * 256 * 4096 + pos0;

    float acc[4][4];
#pragma unroll
    for (int i = 0; i < 4; i++)
#pragma unroll
        for (int j = 0; j < 4; j++) acc[i][j] = 0.f;

    for (int kc = 0; kc < 256; kc += 32) {
        __syncthreads();
        for (int i = t; i < 32 * 128; i += 256) {
            int k = i >> 7, mm = i & 127;
            Xs[k][mm] = xb[(size_t)(kc + k) * 4096 + mm];
        }
        for (int i = t; i < 32 * 32; i += 256) {
            int oc = i >> 5, k = i & 31;
            Ws[k][oc] = w[oc * 256 + kc + k];
        }
        __syncthreads();
#pragma unroll
        for (int k = 0; k < 32; k++) {
            float4 wv = *(const float4*)&Ws[k][oc0];
            float wr[4]; *(float4*)wr = wv;
            float4 xv = *(const float4*)&Xs[k][m0];
#pragma unroll
            for (int i = 0; i < 4; i++) {
                acc[i][0] += wr[i] * xv.x; acc[i][1] += wr[i] * xv.y;
                acc[i][2] += wr[i] * xv.z; acc[i][3] += wr[i] * xv.w;
            }
        }
    }
#pragma unroll
    for (int i = 0; i < 4; i++) {
        int oc = oc0 + i;
        float al = cs[oc] * rsqrtf(cv[oc] + EPSV);
        float bc = (cb[oc] - cm[oc]) * al + ct[oc];
        float4 o4;
        o4.x = fmaxf(acc[i][0] * al + bc, 0.f);
        o4.y = fmaxf(acc[i][1] * al + bc, 0.f);
        o4.z = fmaxf(acc[i][2] * al + bc, 0.f);
        o4.w = fmaxf(acc[i][3] * al + bc, 0.f);
        *(float4*)(d_G + (size_t)b * 131072 + (size_t)oc * 4096 + pos0 + m0) = o4;
    }
}

// ---------------------------------------------------------------------------
// conv3: 1x1 conv (256->128) + BN + ReLU + 2x2 maxpool -> d_HH[b][c][n]
// grid (32 row-pairs, 8 batches), 256 threads. 8 oc x (4 cols rowA + 4 cols rowB).
// ---------------------------------------------------------------------------
__global__ void __launch_bounds__(256) conv3_kernel(
    const float* __restrict__ x, const float* __restrict__ w,
    const float* __restrict__ cb, const float* __restrict__ cs,
    const float* __restrict__ ct, const float* __restrict__ cm,
    const float* __restrict__ cv)
{
    int b = blockIdx.y;
    int r = blockIdx.x;
    int t = threadIdx.x;
    int og = t >> 4, mg = t & 15;
    int oc0 = og * 8;
    int m0a = mg * 4;

    __shared__ float Xs[32][128];
    __shared__ float Ws[32][128];

    const float* xb = x + (size_t)b * 256 * 4096 + (size_t)r * 128;

    float aa[8][4], ab[8][4];
#pragma unroll
    for (int i = 0; i < 8; i++)
#pragma unroll
        for (int j = 0; j < 4; j++) { aa[i][j] = 0.f; ab[i][j] = 0.f; }

    for (int kc = 0; kc < 256; kc += 32) {
        __syncthreads();
        for (int i = t; i < 32 * 128; i += 256) {
            int k = i >> 7, mm = i & 127;
            Xs[k][mm] = xb[(size_t)(kc + k) * 4096 + mm];
        }
        for (int i = t; i < 32 * 128; i += 256) {
            int oc = i >> 5, k = i & 31;
            Ws[k][oc] = w[oc * 256 + kc + k];
        }
        __syncthreads();
#pragma unroll
        for (int k = 0; k < 32; k++) {
            float wr[8];
            *(float4*)&wr[0] = *(const float4*)&Ws[k][oc0];
            *(float4*)&wr[4] = *(const float4*)&Ws[k][oc0 + 4];
            float4 xa = *(const float4*)&Xs[k][m0a];
            float4 xv2 = *(const float4*)&Xs[k][m0a + 64];
#pragma unroll
            for (int i = 0; i < 8; i++) {
                aa[i][0] += wr[i] * xa.x;  aa[i][1] += wr[i] * xa.y;
                aa[i][2] += wr[i] * xa.z;  aa[i][3] += wr[i] * xa.w;
                ab[i][0] += wr[i] * xv2.x; ab[i][1] += wr[i] * xv2.y;
                ab[i][2] += wr[i] * xv2.z; ab[i][3] += wr[i] * xv2.w;
            }
        }
    }
#pragma unroll
    for (int i = 0; i < 8; i++) {
        int oc = oc0 + i;
        float al = cs[oc] * rsqrtf(cv[oc] + EPSV);
        float bc = (cb[oc] - cm[oc]) * al + ct[oc];
        float va[4], vb[4];
#pragma unroll
        for (int j = 0; j < 4; j++) {
            va[j] = fmaxf(aa[i][j] * al + bc, 0.f);
            vb[j] = fmaxf(ab[i][j] * al + bc, 0.f);
        }
        float p0 = fmaxf(fmaxf(va[0], va[1]), fmaxf(vb[0], vb[1]));
        float p1 = fmaxf(fmaxf(va[2], va[3]), fmaxf(vb[2], vb[3]));
        float2 o2 = make_float2(p0, p1);
        *(float2*)(d_HH + (size_t)b * 131072 + (size_t)oc * 1024 + r * 32 + mg * 2) = o2;
    }
}

// ---------------------------------------------------------------------------
// Fused flash-style attention:
//   s[n,m] = sum_k f[n,k] * g[k,m];  beta = softmax over n;  o[c,m] = hh[c,:] @ beta[:,m]
// grid (64 m-tiles of 64, 8 batches), 256 threads.
// Thread layout: m_loc = t&63 (one m per thread column), cg = t>>6 (4 groups of 32 c).
// ---------------------------------------------------------------------------
__global__ void __launch_bounds__(256) attn_kernel()
{
    int b = blockIdx.y;
    int m0 = blockIdx.x * 64;
    int t = threadIdx.x;
    int ml = t & 63, cg = t >> 6;
    int m = m0 + ml;

    const float* gB = d_G + (size_t)b * 131072;
    const float* fB = d_F + (size_t)b * 32768;
    const float* hB = d_HH + (size_t)b * 131072;

    __shared__ float Ft[32][32];   // [n_local][k]
    __shared__ float Ht[128][32];  // [c][n_local]
    __shared__ float St[32][64];   // [n_local][m_local]

    float gq[32];
#pragma unroll
    for (int k = 0; k < 32; k++) gq[k] = gB[(size_t)k * 4096 + m];

    float o_acc[32];
#pragma unroll
    for (int c = 0; c < 32; c++) o_acc[c] = 0.f;
    float row_max = -1e30f, row_sum = 0.f;

    for (int n0 = 0; n0 < 1024; n0 += 32) {
        __syncthreads();
        // f chunk: 32 rows x 32 k = 4KB, contiguous in global
        ((float4*)Ft)[t] = ((const float4*)(fB + (size_t)n0 * 32))[t];
        // hh chunk: 128 c x 32 n
#pragma unroll
        for (int j = 0; j < 4; j++) {
            int i = t + j * 256;
            int c = i >> 3, vq = i & 7;
            ((float4*)&Ht[c][0])[vq] = ((const float4*)(hB + (size_t)c * 1024 + n0))[vq];
        }
        __syncthreads();

        // s tile: each thread computes 8 n for its m
#pragma unroll
        for (int i = 0; i < 8; i++) {
            int n = cg * 8 + i;
            float acc = 0.f;
#pragma unroll
            for (int k4 = 0; k4 < 8; k4++) {
                float4 fv = ((const float4*)&Ft[n][0])[k4];
                acc += fv.x * gq[k4 * 4] + fv.y * gq[k4 * 4 + 1] +
                       fv.z * gq[k4 * 4 + 2] + fv.w * gq[k4 * 4 + 3];
            }
            St[n][ml] = acc;
        }
        __syncthreads();

        // online softmax update for this thread's m
        float cmax = row_max;
#pragma unroll
        for (int n = 0; n < 32; n++) cmax = fmaxf(cmax, St[n][ml]);
        float scale = __expf(row_max - cmax);
        row_sum *= scale;
#pragma unroll
        for (int c = 0; c < 32; c++) o_acc[c] *= scale;
        row_max = cmax;

        float p[32];
#pragma unroll
        for (int n = 0; n < 32; n++) p[n] = __expf(St[n][ml] - cmax);
#pragma unroll
        for (int n = 0; n < 32; n++) row_sum += p[n];

        // o accumulation: 32 c owned by this thread
#pragma unroll
        for (int c = 0; c < 32; c++) {
            float a = o_acc[c];
#pragma unroll
            for (int n4 = 0; n4 < 8; n4++) {
                float4 hv = ((const float4*)&Ht[cg * 32 + c][0])[n4];
                a += p[n4 * 4] * hv.x + p[n4 * 4 + 1] * hv.y +
                     p[n4 * 4 + 2] * hv.z + p[n4 * 4 + 3] * hv.w;
            }
            o_acc[c] = a;
        }
    }

    float inv = 1.f / row_sum;
    float* oB = d_O + (size_t)b * 524288;
#pragma unroll
    for (int c = 0; c < 32; c++)
        oB[(size_t)(cg * 32 + c) * 4096 + m] = o_acc[c] * inv;
}

// ---------------------------------------------------------------------------
// conv4: 1x1 conv (128->256) + BN (no ReLU), out = gamma*bn + x
// grid (32 m-tiles, 4 oc-tiles of 64, 8 batches), 256 threads.
// Thread: 4 oc x (4 m + 4 m at +64) — fully coalesced float4 stores.
// ---------------------------------------------------------------------------
__global__ void __launch_bounds__(256) conv4_kernel(
    const float* __restrict__ x, const float* __restrict__ w,
    const float* __restrict__ cb, const float* __restrict__ cs,
    const float* __restrict__ ct, const float* __restrict__ cm,
    const float* __restrict__ cv, const float* __restrict__ gamma,
    float* __restrict__ out)
{
    int b = blockIdx.z;
    int OC0 = blockIdx.y * 64;
    int pos0 = blockIdx.x * 128;
    int t = threadIdx.x;
    int og = t >> 4, mg = t & 15;
    int oc0l = og * 4;
    int m0a = mg * 4;

    __shared__ float Xs[32][128];
    __shared__ float Ws[32][64];

    const float* ob = d_O + (size_t)b * 524288 + pos0;

    float aa[4][4], ab[4][4];
#pragma unroll
    for (int i = 0; i < 4; i++)
#pragma unroll
        for (int j = 0; j < 4; j++) { aa[i][j] = 0.f; ab[i][j] = 0.f; }

    for (int kc = 0; kc < 128; kc += 32) {
        __syncthreads();
        for (int i = t; i < 32 * 128; i += 256) {
            int k = i >> 7, mm = i & 127;
            Xs[k][mm] = ob[(size_t)(kc + k) * 4096 + mm];
        }
        for (int i = t; i < 32 * 64; i += 256) {
            int oc = i >> 5, k = i & 31;
            Ws[k][oc] = w[(OC0 + oc) * 128 + kc + k];
        }
        __syncthreads();
#pragma unroll
        for (int k = 0; k < 32; k++) {
            float4 wv = *(const float4*)&Ws[k][oc0l];
            float wr[4]; *(float4*)wr = wv;
            float4 xa = *(const float4*)&Xs[k][m0a];
            float4 xv2 = *(const float4*)&Xs[k][m0a + 64];
#pragma unroll
            for (int i = 0; i < 4; i++) {
                aa[i][0] += wr[i] * xa.x;  aa[i][1] += wr[i] * xa.y;
                aa[i][2] += wr[i] * xa.z;  aa[i][3] += wr[i] * xa.w;
                ab[i][0] += wr[i] * xv2.x; ab[i][1] += wr[i] * xv2.y;
                ab[i][2] += wr[i] * xv2.z; ab[i][3] += wr[i] * xv2.w;
            }
        }
    }
    float gm = *gamma;
#pragma unroll
    for (int i = 0; i < 4; i++) {
        int oc = OC0 + oc0l + i;
        float al = cs[oc] * rsqrtf(cv[oc] + EPSV);
        float bc = (cb[oc] - cm[oc]) * al + ct[oc];
        size_t base = (size_t)b * 1048576 + (size_t)oc * 4096 + pos0;

        float4 xv = *(const float4*)(x + base + m0a);
        float4 r4;
        r4.x = gm * (aa[i][0] * al + bc) + xv.x;
        r4.y = gm * (aa[i][1] * al + bc) + xv.y;
        r4.z = gm * (aa[i][2] * al + bc) + xv.z;
        r4.w = gm * (aa[i][3] * al + bc) + xv.w;
        *(float4*)(out + base + m0a) = r4;

        float4 xw = *(const float4*)(x + base + m0a + 64);
        float4 s4;
        s4.x = gm * (ab[i][0] * al + bc) + xw.x;
        s4.y = gm * (ab[i][1] * al + bc) + xw.y;
        s4.z = gm * (ab[i][2] * al + bc) + xw.z;
        s4.w = gm * (ab[i][3] * al + bc) + xw.w;
        *(float4*)(out + base + m0a + 64) = s4;
    }
}

// ---------------------------------------------------------------------------
extern "C" void kernel_launch(void* const* d_in, const int* in_sizes, int n_in,
                              void* d_out, int out_size)
{
    const float* x = (const float*)d_in[0];
    // conv param groups: w, b, s, t, m, v at 1+6*(i-1)
    const float* w1 = (const float*)d_in[1];
    const float* b1 = (const float*)d_in[2];
    const float* s1 = (const float*)d_in[3];
    const float* t1 = (const float*)d_in[4];
    const float* m1 = (const float*)d_in[5];
    const float* v1 = (const float*)d_in[6];
    const float* w2 = (const float*)d_in[7];
    const float* b2 = (const float*)d_in[8];
    const float* s2 = (const float*)d_in[9];
    const float* t2 = (const float*)d_in[10];
    const float* m2 = (const float*)d_in[11];
    const float* v2 = (const float*)d_in[12];
    const float* w3 = (const float*)d_in[13];
    const float* b3 = (const float*)d_in[14];
    const float* s3 = (const float*)d_in[15];
    const float* t3 = (const float*)d_in[16];
    const float* m3 = (const float*)d_in[17];
    const float* v3 = (const float*)d_in[18];
    const float* w4 = (const float*)d_in[19];
    const float* b4 = (const float*)d_in[20];
    const float* s4 = (const float*)d_in[21];
    const float* t4 = (const float*)d_in[22];
    const float* m4 = (const float*)d_in[23];
    const float* v4 = (const float*)d_in[24];
    const float* gamma = (const float*)d_in[25];

    conv1_kernel<<<dim3(32, 8), 256>>>(x, w1, b1, s1, t1, m1, v1);
    conv2_kernel<<<dim3(32, 8), 256>>>(x, w2, b2, s2, t2, m2, v2);
    conv3_kernel<<<dim3(32, 8), 256>>>(x, w3, b3, s3, t3, m3, v3);
    attn_kernel<<<dim3(64, 8), 256>>>();
    conv4_kernel<<<dim3(32, 4, 8), 256>>>(x, w4, b4, s4, t4, m4, v4, gamma,
                                          (float*)d_out);
}

// round 6
// speedup vs baseline: 1.2769x; 1.2769x over previous
#include <cuda_runtime.h>

#define EPSV 1e-5f

// ---------------- scratch (device globals; no cudaMalloc allowed) ----------
__device__ float d_F[8 * 1024 * 32];    // f: [b][n=1024][k=32]   (pooled conv1, transposed)
__device__ float d_G[8 * 32 * 4096];    // g: [b][k=32][m=4096]   (conv2)
__device__ float d_HH[8 * 128 * 1024];  // hh:[b][c=128][n=1024]  (pooled conv3)
__device__ float d_O[8 * 128 * 4096];   // o: [b][c=128][m=4096]  (attention out)

// ---------------- packed f32x2 helpers (sm_100+ FFMA2) ----------------------
__device__ __forceinline__ unsigned long long pk2(float a, float b) {
    unsigned long long r;
    asm("mov.b64 %0, {%1, %2};" : "=l"(r) : "f"(a), "f"(b));
    return r;
}
__device__ __forceinline__ void fma2(unsigned long long& d,
                                     unsigned long long a, unsigned long long b) {
    asm("fma.rn.f32x2 %0, %1, %2, %0;" : "+l"(d) : "l"(a), "l"(b));
}
__device__ __forceinline__ void mul2(unsigned long long& d, unsigned long long a) {
    asm("mul.rn.f32x2 %0, %0, %1;" : "+l"(d) : "l"(a));
}
__device__ __forceinline__ float2 upk(unsigned long long v) {
    float2 f;
    asm("mov.b64 {%0, %1}, %2;" : "=f"(f.x), "=f"(f.y) : "l"(v));
    return f;
}

// ---------------------------------------------------------------------------
// conv1: 1x1 conv (256->32) + BN + ReLU + 2x2 maxpool  -> d_F[b][n][k]
// ---------------------------------------------------------------------------
__global__ void __launch_bounds__(256) conv1_kernel(
    const float* __restrict__ x, const float* __restrict__ w,
    const float* __restrict__ cb, const float* __restrict__ cs,
    const float* __restrict__ ct, const float* __restrict__ cm,
    const float* __restrict__ cv)
{
    int b = blockIdx.y;
    int r = blockIdx.x;
    int t = threadIdx.x;
    int og = t >> 5, mg = t & 31;
    int oc0 = og * 4;
    int m0a = mg * 2;

    __shared__ float Xs[32][128];
    __shared__ float Ws[32][32];

    const float* xb = x + (size_t)b * 256 * 4096 + (size_t)r * 128;

    unsigned long long pa[4], pb[4];
#pragma unroll
    for (int i = 0; i < 4; i++) { pa[i] = 0ull; pb[i] = 0ull; }

    for (int kc = 0; kc < 256; kc += 32) {
        __syncthreads();
        for (int i = t; i < 32 * 128; i += 256) {
            int k = i >> 7, mm = i & 127;
            Xs[k][mm] = xb[(size_t)(kc + k) * 4096 + mm];
        }
        for (int i = t; i < 32 * 32; i += 256) {
            int oc = i >> 5, k = i & 31;
            Ws[k][oc] = w[oc * 256 + kc + k];
        }
        __syncthreads();
#pragma unroll
        for (int k = 0; k < 32; k++) {
            float4 wv = *(const float4*)&Ws[k][oc0];
            unsigned long long ww[4];
            ww[0] = pk2(wv.x, wv.x); ww[1] = pk2(wv.y, wv.y);
            ww[2] = pk2(wv.z, wv.z); ww[3] = pk2(wv.w, wv.w);
            unsigned long long xa = *(const unsigned long long*)&Xs[k][m0a];
            unsigned long long xb2 = *(const unsigned long long*)&Xs[k][m0a + 64];
#pragma unroll
            for (int i = 0; i < 4; i++) { fma2(pa[i], ww[i], xa); fma2(pb[i], ww[i], xb2); }
        }
    }
    float rr[4];
#pragma unroll
    for (int i = 0; i < 4; i++) {
        int oc = oc0 + i;
        float al = cs[oc] * rsqrtf(cv[oc] + EPSV);
        float bc = (cb[oc] - cm[oc]) * al + ct[oc];
        float2 va = upk(pa[i]);
        float2 vb = upk(pb[i]);
        float v0 = fmaxf(va.x * al + bc, 0.f);
        float v1 = fmaxf(va.y * al + bc, 0.f);
        float v2 = fmaxf(vb.x * al + bc, 0.f);
        float v3 = fmaxf(vb.y * al + bc, 0.f);
        rr[i] = fmaxf(fmaxf(v0, v1), fmaxf(v2, v3));
    }
    float* fout = d_F + (size_t)b * 32768 + (size_t)(r * 32 + mg) * 32 + oc0;
    *(float4*)fout = *(float4*)rr;
}

// ---------------------------------------------------------------------------
// conv2: 1x1 conv (256->32) + BN + ReLU -> d_G[b][k][m]
// ---------------------------------------------------------------------------
__global__ void __launch_bounds__(256) conv2_kernel(
    const float* __restrict__ x, const float* __restrict__ w,
    const float* __restrict__ cb, const float* __restrict__ cs,
    const float* __restrict__ ct, const float* __restrict__ cm,
    const float* __restrict__ cv)
{
    int b = blockIdx.y;
    int pos0 = blockIdx.x * 128;
    int t = threadIdx.x;
    int og = t >> 5, mg = t & 31;
    int oc0 = og * 4;
    int m0 = mg * 4;

    __shared__ float Xs[32][128];
    __shared__ float Ws[32][32];

    const float* xb = x + (size_t)b * 256 * 4096 + pos0;

    unsigned long long acc[4][2];
#pragma unroll
    for (int i = 0; i < 4; i++) { acc[i][0] = 0ull; acc[i][1] = 0ull; }

    for (int kc = 0; kc < 256; kc += 32) {
        __syncthreads();
        for (int i = t; i < 32 * 128; i += 256) {
            int k = i >> 7, mm = i & 127;
            Xs[k][mm] = xb[(size_t)(kc + k) * 4096 + mm];
        }
        for (int i = t; i < 32 * 32; i += 256) {
            int oc = i >> 5, k = i & 31;
            Ws[k][oc] = w[oc * 256 + kc + k];
        }
        __syncthreads();
#pragma unroll
        for (int k = 0; k < 32; k++) {
            float4 wv = *(const float4*)&Ws[k][oc0];
            unsigned long long ww[4];
            ww[0] = pk2(wv.x, wv.x); ww[1] = pk2(wv.y, wv.y);
            ww[2] = pk2(wv.z, wv.z); ww[3] = pk2(wv.w, wv.w);
            ulonglong2 xv = *(const ulonglong2*)&Xs[k][m0];
#pragma unroll
            for (int i = 0; i < 4; i++) { fma2(acc[i][0], ww[i], xv.x); fma2(acc[i][1], ww[i], xv.y); }
        }
    }
#pragma unroll
    for (int i = 0; i < 4; i++) {
        int oc = oc0 + i;
        float al = cs[oc] * rsqrtf(cv[oc] + EPSV);
        float bc = (cb[oc] - cm[oc]) * al + ct[oc];
        float2 v0 = upk(acc[i][0]);
        float2 v1 = upk(acc[i][1]);
        float4 o4;
        o4.x = fmaxf(v0.x * al + bc, 0.f);
        o4.y = fmaxf(v0.y * al + bc, 0.f);
        o4.z = fmaxf(v1.x * al + bc, 0.f);
        o4.w = fmaxf(v1.y * al + bc, 0.f);
        *(float4*)(d_G + (size_t)b * 131072 + (size_t)oc * 4096 + pos0 + m0) = o4;
    }
}

// ---------------------------------------------------------------------------
// conv3: 1x1 conv (256->128) + BN + ReLU + 2x2 maxpool -> d_HH[b][c][n]
// ---------------------------------------------------------------------------
__global__ void __launch_bounds__(256) conv3_kernel(
    const float* __restrict__ x, const float* __restrict__ w,
    const float* __restrict__ cb, const float* __restrict__ cs,
    const float* __restrict__ ct, const float* __restrict__ cm,
    const float* __restrict__ cv)
{
    int b = blockIdx.y;
    int r = blockIdx.x;
    int t = threadIdx.x;
    int og = t >> 4, mg = t & 15;
    int oc0 = og * 8;
    int m0a = mg * 4;

    __shared__ float Xs[32][128];
    __shared__ float Ws[32][128];

    const float* xb = x + (size_t)b * 256 * 4096 + (size_t)r * 128;

    unsigned long long aa[8][2], ab[8][2];
#pragma unroll
    for (int i = 0; i < 8; i++) { aa[i][0] = aa[i][1] = 0ull; ab[i][0] = ab[i][1] = 0ull; }

    for (int kc = 0; kc < 256; kc += 32) {
        __syncthreads();
        for (int i = t; i < 32 * 128; i += 256) {
            int k = i >> 7, mm = i & 127;
            Xs[k][mm] = xb[(size_t)(kc + k) * 4096 + mm];
        }
        for (int i = t; i < 32 * 128; i += 256) {
            int oc = i >> 5, k = i & 31;
            Ws[k][oc] = w[oc * 256 + kc + k];
        }
        __syncthreads();
#pragma unroll
        for (int k = 0; k < 32; k++) {
            float wr[8];
            *(float4*)&wr[0] = *(const float4*)&Ws[k][oc0];
            *(float4*)&wr[4] = *(const float4*)&Ws[k][oc0 + 4];
            unsigned long long ww[8];
#pragma unroll
            for (int i = 0; i < 8; i++) ww[i] = pk2(wr[i], wr[i]);
            ulonglong2 xa = *(const ulonglong2*)&Xs[k][m0a];
            ulonglong2 xv2 = *(const ulonglong2*)&Xs[k][m0a + 64];
#pragma unroll
            for (int i = 0; i < 8; i++) {
                fma2(aa[i][0], ww[i], xa.x);  fma2(aa[i][1], ww[i], xa.y);
                fma2(ab[i][0], ww[i], xv2.x); fma2(ab[i][1], ww[i], xv2.y);
            }
        }
    }
#pragma unroll
    for (int i = 0; i < 8; i++) {
        int oc = oc0 + i;
        float al = cs[oc] * rsqrtf(cv[oc] + EPSV);
        float bc = (cb[oc] - cm[oc]) * al + ct[oc];
        float2 a0 = upk(aa[i][0]), a1 = upk(aa[i][1]);
        float2 b0 = upk(ab[i][0]), b1 = upk(ab[i][1]);
        float va0 = fmaxf(a0.x * al + bc, 0.f), va1 = fmaxf(a0.y * al + bc, 0.f);
        float va2 = fmaxf(a1.x * al + bc, 0.f), va3 = fmaxf(a1.y * al + bc, 0.f);
        float vb0 = fmaxf(b0.x * al + bc, 0.f), vb1 = fmaxf(b0.y * al + bc, 0.f);
        float vb2 = fmaxf(b1.x * al + bc, 0.f), vb3 = fmaxf(b1.y * al + bc, 0.f);
        float p0 = fmaxf(fmaxf(va0, va1), fmaxf(vb0, vb1));
        float p1 = fmaxf(fmaxf(va2, va3), fmaxf(vb2, vb3));
        *(float2*)(d_HH + (size_t)b * 131072 + (size_t)oc * 1024 + r * 32 + mg * 2) =
            make_float2(p0, p1);
    }
}

// ---------------------------------------------------------------------------
// Fused flash-style attention (v2, f32x2 register tiling):
// block = 64 m x 128 c, n chunks of 32. 256 threads: cg = t>>4 (8 c), mg = t&15 (4 m).
// ---------------------------------------------------------------------------
__global__ void __launch_bounds__(256, 2) attn_kernel()
{
    int b = blockIdx.y;
    int m0 = blockIdx.x * 64;
    int t = threadIdx.x;
    int cg = t >> 4, mg = t & 15;

    __shared__ float Gs[32][64];    // g[k][m]  (block's queries)
    __shared__ float Ft[32][32];    // f[n_loc][k]
    __shared__ float Hts[32][128];  // hh transposed: [n_loc][c]
    __shared__ float St[32][64];    // s / p tile [n_loc][m_loc]
    __shared__ float RowM[64], RowS[64], RowScale[64];

    const float* gB = d_G + (size_t)b * 131072 + m0;
    const float* fB = d_F + (size_t)b * 32768;
    const float* hB = d_HH + (size_t)b * 131072;

    // load Gs once: 32 k x 64 m
    for (int i = t; i < 32 * 16; i += 256) {
        int k = i >> 4, mq = i & 15;
        ((float4*)&Gs[k][0])[mq] = *(const float4*)(gB + (size_t)k * 4096 + mq * 4);
    }
    if (t < 64) { RowM[t] = -1e30f; RowS[t] = 0.f; }

    unsigned long long acc[4][4];  // [c-pair][m]
#pragma unroll
    for (int i = 0; i < 4; i++)
#pragma unroll
        for (int j = 0; j < 4; j++) acc[i][j] = 0ull;

    for (int n0 = 0; n0 < 1024; n0 += 32) {
        __syncthreads();
        // Ft chunk: 1024 floats contiguous
        ((float4*)Ft)[t] = ((const float4*)(fB + (size_t)n0 * 32))[t];
        // Hts chunk (transpose 128c x 32n): thread: c = t>>1, 16 n starting (t&1)*16
        {
            int c = t >> 1, nq = (t & 1) * 16;
            const float* src = hB + (size_t)c * 1024 + n0 + nq;
            float4 v0 = *(const float4*)(src);
            float4 v1 = *(const float4*)(src + 4);
            float4 v2 = *(const float4*)(src + 8);
            float4 v3 = *(const float4*)(src + 12);
            Hts[nq + 0][c] = v0.x;  Hts[nq + 1][c] = v0.y;
            Hts[nq + 2][c] = v0.z;  Hts[nq + 3][c] = v0.w;
            Hts[nq + 4][c] = v1.x;  Hts[nq + 5][c] = v1.y;
            Hts[nq + 6][c] = v1.z;  Hts[nq + 7][c] = v1.w;
            Hts[nq + 8][c] = v2.x;  Hts[nq + 9][c] = v2.y;
            Hts[nq + 10][c] = v2.z; Hts[nq + 11][c] = v2.w;
            Hts[nq + 12][c] = v3.x; Hts[nq + 13][c] = v3.y;
            Hts[nq + 14][c] = v3.z; Hts[nq + 15][c] = v3.w;
        }
        __syncthreads();

        // s tile: thread computes 2 n (cg*2, cg*2+1) x 4 m (mg*4..), pairs along m
        {
            int na = cg * 2, nb = na + 1;
            unsigned long long s00 = 0ull, s01 = 0ull, s10 = 0ull, s11 = 0ull;
#pragma unroll
            for (int k = 0; k < 32; k++) {
                float f0 = Ft[na][k], f1 = Ft[nb][k];
                unsigned long long ff0 = pk2(f0, f0);
                unsigned long long ff1 = pk2(f1, f1);
                ulonglong2 g2 = *(const ulonglong2*)&Gs[k][mg * 4];
                fma2(s00, ff0, g2.x); fma2(s01, ff0, g2.y);
                fma2(s10, ff1, g2.x); fma2(s11, ff1, g2.y);
            }
            ulonglong2 ra; ra.x = s00; ra.y = s01;
            ulonglong2 rb; rb.x = s10; rb.y = s11;
            *(ulonglong2*)&St[na][mg * 4] = ra;
            *(ulonglong2*)&St[nb][mg * 4] = rb;
        }
        __syncthreads();

        // softmax pass 1: per-column running max
        if (t < 64) {
            float cmax = -1e30f;
#pragma unroll
            for (int n = 0; n < 32; n++) cmax = fmaxf(cmax, St[n][t]);
            float om = RowM[t];
            float nm = fmaxf(om, cmax);
            RowScale[t] = __expf(om - nm);
            RowM[t] = nm;
        }
        __syncthreads();

        // p = exp(s - max) in place; rescale o accumulators
        {
            int n = t >> 3, mq = (t & 7) * 8;
            float4 a = *(float4*)&St[n][mq];
            float4 bb = *(float4*)&St[n][mq + 4];
            a.x = __expf(a.x - RowM[mq + 0]);
            a.y = __expf(a.y - RowM[mq + 1]);
            a.z = __expf(a.z - RowM[mq + 2]);
            a.w = __expf(a.w - RowM[mq + 3]);
            bb.x = __expf(bb.x - RowM[mq + 4]);
            bb.y = __expf(bb.y - RowM[mq + 5]);
            bb.z = __expf(bb.z - RowM[mq + 6]);
            bb.w = __expf(bb.w - RowM[mq + 7]);
            *(float4*)&St[n][mq] = a;
            *(float4*)&St[n][mq + 4] = bb;
        }
        {
            unsigned long long sc[4];
#pragma unroll
            for (int j = 0; j < 4; j++) {
                float s = RowScale[mg * 4 + j];
                sc[j] = pk2(s, s);
            }
#pragma unroll
            for (int i = 0; i < 4; i++)
#pragma unroll
                for (int j = 0; j < 4; j++) mul2(acc[i][j], sc[j]);
        }
        __syncthreads();

        // column sums (running)
        if (t < 64) {
            float s = 0.f;
#pragma unroll
            for (int n = 0; n < 32; n++) s += St[n][t];
            RowS[t] = RowS[t] * RowScale[t] + s;
        }

        // pV: acc[c-pair][m] += h[c-pair](n) * p[n][m]
#pragma unroll
        for (int n = 0; n < 32; n++) {
            float4 p4 = *(float4*)&St[n][mg * 4];
            unsigned long long pp0 = pk2(p4.x, p4.x);
            unsigned long long pp1 = pk2(p4.y, p4.y);
            unsigned long long pp2 = pk2(p4.z, p4.z);
            unsigned long long pp3 = pk2(p4.w, p4.w);
            const unsigned long long* hrow = (const unsigned long long*)&Hts[n][cg * 8];
            unsigned long long h0 = hrow[0], h1 = hrow[1], h2 = hrow[2], h3 = hrow[3];
            fma2(acc[0][0], h0, pp0); fma2(acc[0][1], h0, pp1);
            fma2(acc[0][2], h0, pp2); fma2(acc[0][3], h0, pp3);
            fma2(acc[1][0], h1, pp0); fma2(acc[1][1], h1, pp1);
            fma2(acc[1][2], h1, pp2); fma2(acc[1][3], h1, pp3);
            fma2(acc[2][0], h2, pp0); fma2(acc[2][1], h2, pp1);
            fma2(acc[2][2], h2, pp2); fma2(acc[2][3], h2, pp3);
            fma2(acc[3][0], h3, pp0); fma2(acc[3][1], h3, pp1);
            fma2(acc[3][2], h3, pp2); fma2(acc[3][3], h3, pp3);
        }
    }

    __syncthreads();
    float inv[4];
#pragma unroll
    for (int j = 0; j < 4; j++) inv[j] = 1.f / RowS[mg * 4 + j];

    float* oB = d_O + (size_t)b * 524288;
#pragma unroll
    for (int cp = 0; cp < 4; cp++) {
        float2 v0 = upk(acc[cp][0]);
        float2 v1 = upk(acc[cp][1]);
        float2 v2 = upk(acc[cp][2]);
        float2 v3 = upk(acc[cp][3]);
        int c0 = cg * 8 + cp * 2;
        float4 r0, r1;
        r0.x = v0.x * inv[0]; r0.y = v1.x * inv[1]; r0.z = v2.x * inv[2]; r0.w = v3.x * inv[3];
        r1.x = v0.y * inv[0]; r1.y = v1.y * inv[1]; r1.z = v2.y * inv[2]; r1.w = v3.y * inv[3];
        *(float4*)(oB + (size_t)c0 * 4096 + m0 + mg * 4) = r0;
        *(float4*)(oB + (size_t)(c0 + 1) * 4096 + m0 + mg * 4) = r1;
    }
}

// ---------------------------------------------------------------------------
// conv4: 1x1 conv (128->256) + BN (no ReLU), out = gamma*bn + x
// ---------------------------------------------------------------------------
__global__ void __launch_bounds__(256) conv4_kernel(
    const float* __restrict__ x, const float* __restrict__ w,
    const float* __restrict__ cb, const float* __restrict__ cs,
    const float* __restrict__ ct, const float* __restrict__ cm,
    const float* __restrict__ cv, const float* __restrict__ gamma,
    float* __restrict__ out)
{
    int b = blockIdx.z;
    int OC0 = blockIdx.y * 64;
    int pos0 = blockIdx.x * 128;
    int t = threadIdx.x;
    int og = t >> 4, mg = t & 15;
    int oc0l = og * 4;
    int m0a = mg * 4;

    __shared__ float Xs[32][128];
    __shared__ float Ws[32][64];

    const float* ob = d_O + (size_t)b * 524288 + pos0;

    unsigned long long aa[4][2], ab[4][2];
#pragma unroll
    for (int i = 0; i < 4; i++) { aa[i][0] = aa[i][1] = 0ull; ab[i][0] = ab[i][1] = 0ull; }

    for (int kc = 0; kc < 128; kc += 32) {
        __syncthreads();
        for (int i = t; i < 32 * 128; i += 256) {
            int k = i >> 7, mm = i & 127;
            Xs[k][mm] = ob[(size_t)(kc + k) * 4096 + mm];
        }
        for (int i = t; i < 32 * 64; i += 256) {
            int oc = i >> 5, k = i & 31;
            Ws[k][oc] = w[(OC0 + oc) * 128 + kc + k];
        }
        __syncthreads();
#pragma unroll
        for (int k = 0; k < 32; k++) {
            float4 wv = *(const float4*)&Ws[k][oc0l];
            unsigned long long ww[4];
            ww[0] = pk2(wv.x, wv.x); ww[1] = pk2(wv.y, wv.y);
            ww[2] = pk2(wv.z, wv.z); ww[3] = pk2(wv.w, wv.w);
            ulonglong2 xa = *(const ulonglong2*)&Xs[k][m0a];
            ulonglong2 xv2 = *(const ulonglong2*)&Xs[k][m0a + 64];
#pragma unroll
            for (int i = 0; i < 4; i++) {
                fma2(aa[i][0], ww[i], xa.x);  fma2(aa[i][1], ww[i], xa.y);
                fma2(ab[i][0], ww[i], xv2.x); fma2(ab[i][1], ww[i], xv2.y);
            }
        }
    }
    float gm = *gamma;
#pragma unroll
    for (int i = 0; i < 4; i++) {
        int oc = OC0 + oc0l + i;
        float al = cs[oc] * rsqrtf(cv[oc] + EPSV);
        float bc = (cb[oc] - cm[oc]) * al + ct[oc];
        size_t base = (size_t)b * 1048576 + (size_t)oc * 4096 + pos0;

        float2 a0 = upk(aa[i][0]), a1 = upk(aa[i][1]);
        float4 xv = *(const float4*)(x + base + m0a);
        float4 r4;
        r4.x = gm * (a0.x * al + bc) + xv.x;
        r4.y = gm * (a0.y * al + bc) + xv.y;
        r4.z = gm * (a1.x * al + bc) + xv.z;
        r4.w = gm * (a1.y * al + bc) + xv.w;
        *(float4*)(out + base + m0a) = r4;

        float2 b0 = upk(ab[i][0]), b1 = upk(ab[i][1]);
        float4 xw = *(const float4*)(x + base + m0a + 64);
        float4 s4;
        s4.x = gm * (b0.x * al + bc) + xw.x;
        s4.y = gm * (b0.y * al + bc) + xw.y;
        s4.z = gm * (b1.x * al + bc) + xw.z;
        s4.w = gm * (b1.y * al + bc) + xw.w;
        *(float4*)(out + base + m0a + 64) = s4;
    }
}

// ---------------------------------------------------------------------------
extern "C" void kernel_launch(void* const* d_in, const int* in_sizes, int n_in,
                              void* d_out, int out_size)
{
    const float* x = (const float*)d_in[0];
    const float* w1 = (const float*)d_in[1];
    const float* b1 = (const float*)d_in[2];
    const float* s1 = (const float*)d_in[3];
    const float* t1 = (const float*)d_in[4];
    const float* m1 = (const float*)d_in[5];
    const float* v1 = (const float*)d_in[6];
    const float* w2 = (const float*)d_in[7];
    const float* b2 = (const float*)d_in[8];
    const float* s2 = (const float*)d_in[9];
    const float* t2 = (const float*)d_in[10];
    const float* m2 = (const float*)d_in[11];
    const float* v2 = (const float*)d_in[12];
    const float* w3 = (const float*)d_in[13];
    const float* b3 = (const float*)d_in[14];
    const float* s3 = (const float*)d_in[15];
    const float* t3 = (const float*)d_in[16];
    const float* m3 = (const float*)d_in[17];
    const float* v3 = (const float*)d_in[18];
    const float* w4 = (const float*)d_in[19];
    const float* b4 = (const float*)d_in[20];
    const float* s4 = (const float*)d_in[21];
    const float* t4 = (const float*)d_in[22];
    const float* m4 = (const float*)d_in[23];
    const float* v4 = (const float*)d_in[24];
    const float* gamma = (const float*)d_in[25];

    conv1_kernel<<<dim3(32, 8), 256>>>(x, w1, b1, s1, t1, m1, v1);
    conv2_kernel<<<dim3(32, 8), 256>>>(x, w2, b2, s2, t2, m2, v2);
    conv3_kernel<<<dim3(32, 8), 256>>>(x, w3, b3, s3, t3, m3, v3);
    attn_kernel<<<dim3(64, 8), 256>>>();
    conv4_kernel<<<dim3(32, 4, 8), 256>>>(x, w4, b4, s4, t4, m4, v4, gamma,
                                          (float*)d_out);
}

// round 7
// speedup vs baseline: 2.0525x; 1.6074x over previous
#include <cuda_runtime.h>
#include <cuda_bf16.h>

#define EPSV 1e-5f

// ---------------- scratch (device globals; no cudaMalloc allowed) ----------
__device__ __nv_bfloat16 d_Fh[8 * 1024 * 32];    // f:  [b][n=1024][k=32]
__device__ __nv_bfloat16 d_Ght[8 * 4096 * 32];   // g^T:[b][m=4096][k=32]
__device__ __nv_bfloat16 d_Hh[8 * 128 * 1024];   // hh: [b][c=128][n=1024]
__device__ float d_O[8 * 128 * 4096];            // o:  [b][c=128][m=4096]

// ---------------- packed f32x2 helpers (sm_100+ FFMA2) ----------------------
__device__ __forceinline__ unsigned long long pk2(float a, float b) {
    unsigned long long r;
    asm("mov.b64 %0, {%1, %2};" : "=l"(r) : "f"(a), "f"(b));
    return r;
}
__device__ __forceinline__ void fma2(unsigned long long& d,
                                     unsigned long long a, unsigned long long b) {
    asm("fma.rn.f32x2 %0, %1, %2, %0;" : "+l"(d) : "l"(a), "l"(b));
}
__device__ __forceinline__ float2 upk(unsigned long long v) {
    float2 f;
    asm("mov.b64 {%0, %1}, %2;" : "=f"(f.x), "=f"(f.y) : "l"(v));
    return f;
}

// ---------------- bf16 mma helper -------------------------------------------
__device__ __forceinline__ void mma_bf16(float c[4], unsigned a0, unsigned a1,
                                         unsigned a2, unsigned a3,
                                         unsigned b0, unsigned b1) {
    asm volatile(
        "mma.sync.aligned.m16n8k16.row.col.f32.bf16.bf16.f32 "
        "{%0,%1,%2,%3}, {%4,%5,%6,%7}, {%8,%9}, {%0,%1,%2,%3};"
        : "+f"(c[0]), "+f"(c[1]), "+f"(c[2]), "+f"(c[3])
        : "r"(a0), "r"(a1), "r"(a2), "r"(a3), "r"(b0), "r"(b1));
}

// ---------------------------------------------------------------------------
// conv1: 1x1 conv (256->32) + BN + ReLU + 2x2 maxpool -> d_Fh[b][n][k] (bf16)
// ---------------------------------------------------------------------------
__global__ void __launch_bounds__(256) conv1_kernel(
    const float* __restrict__ x, const float* __restrict__ w,
    const float* __restrict__ cb, const float* __restrict__ cs,
    const float* __restrict__ ct, const float* __restrict__ cm,
    const float* __restrict__ cv)
{
    int b = blockIdx.y;
    int r = blockIdx.x;
    int t = threadIdx.x;
    int og = t >> 5, mg = t & 31;
    int oc0 = og * 4;
    int m0a = mg * 2;

    __shared__ float Xs[32][128];
    __shared__ float Ws[32][32];

    const float* xb = x + (size_t)b * 256 * 4096 + (size_t)r * 128;

    unsigned long long pa[4], pb[4];
#pragma unroll
    for (int i = 0; i < 4; i++) { pa[i] = 0ull; pb[i] = 0ull; }

    for (int kc = 0; kc < 256; kc += 32) {
        __syncthreads();
        for (int i = t; i < 32 * 128; i += 256) {
            int k = i >> 7, mm = i & 127;
            Xs[k][mm] = xb[(size_t)(kc + k) * 4096 + mm];
        }
        for (int i = t; i < 32 * 32; i += 256) {
            int oc = i >> 5, k = i & 31;
            Ws[k][oc] = w[oc * 256 + kc + k];
        }
        __syncthreads();
#pragma unroll
        for (int k = 0; k < 32; k++) {
            float4 wv = *(const float4*)&Ws[k][oc0];
            unsigned long long ww[4];
            ww[0] = pk2(wv.x, wv.x); ww[1] = pk2(wv.y, wv.y);
            ww[2] = pk2(wv.z, wv.z); ww[3] = pk2(wv.w, wv.w);
            unsigned long long xa = *(const unsigned long long*)&Xs[k][m0a];
            unsigned long long xb2 = *(const unsigned long long*)&Xs[k][m0a + 64];
#pragma unroll
            for (int i = 0; i < 4; i++) { fma2(pa[i], ww[i], xa); fma2(pb[i], ww[i], xb2); }
        }
    }
    float rr[4];
#pragma unroll
    for (int i = 0; i < 4; i++) {
        int oc = oc0 + i;
        float al = cs[oc] * rsqrtf(cv[oc] + EPSV);
        float bc = (cb[oc] - cm[oc]) * al + ct[oc];
        float2 va = upk(pa[i]);
        float2 vb = upk(pb[i]);
        float v0 = fmaxf(va.x * al + bc, 0.f);
        float v1 = fmaxf(va.y * al + bc, 0.f);
        float v2 = fmaxf(vb.x * al + bc, 0.f);
        float v3 = fmaxf(vb.y * al + bc, 0.f);
        rr[i] = fmaxf(fmaxf(v0, v1), fmaxf(v2, v3));
    }
    __nv_bfloat162 h0 = __floats2bfloat162_rn(rr[0], rr[1]);
    __nv_bfloat162 h1 = __floats2bfloat162_rn(rr[2], rr[3]);
    uint2 u;
    u.x = *(unsigned*)&h0;
    u.y = *(unsigned*)&h1;
    *(uint2*)(d_Fh + (size_t)b * 32768 + (size_t)(r * 32 + mg) * 32 + oc0) = u;
}

// ---------------------------------------------------------------------------
// conv2: 1x1 conv (256->32) + BN + ReLU -> d_Ght[b][m][k] (bf16, transposed)
// ---------------------------------------------------------------------------
__global__ void __launch_bounds__(256) conv2_kernel(
    const float* __restrict__ x, const float* __restrict__ w,
    const float* __restrict__ cb, const float* __restrict__ cs,
    const float* __restrict__ ct, const float* __restrict__ cm,
    const float* __restrict__ cv)
{
    int b = blockIdx.y;
    int pos0 = blockIdx.x * 128;
    int t = threadIdx.x;
    int og = t >> 5, mg = t & 31;
    int oc0 = og * 4;
    int m0 = mg * 4;

    __shared__ float Xs[32][128];
    __shared__ float Ws[32][32];

    const float* xb = x + (size_t)b * 256 * 4096 + pos0;

    unsigned long long acc[4][2];
#pragma unroll
    for (int i = 0; i < 4; i++) { acc[i][0] = 0ull; acc[i][1] = 0ull; }

    for (int kc = 0; kc < 256; kc += 32) {
        __syncthreads();
        for (int i = t; i < 32 * 128; i += 256) {
            int k = i >> 7, mm = i & 127;
            Xs[k][mm] = xb[(size_t)(kc + k) * 4096 + mm];
        }
        for (int i = t; i < 32 * 32; i += 256) {
            int oc = i >> 5, k = i & 31;
            Ws[k][oc] = w[oc * 256 + kc + k];
        }
        __syncthreads();
#pragma unroll
        for (int k = 0; k < 32; k++) {
            float4 wv = *(const float4*)&Ws[k][oc0];
            unsigned long long ww[4];
            ww[0] = pk2(wv.x, wv.x); ww[1] = pk2(wv.y, wv.y);
            ww[2] = pk2(wv.z, wv.z); ww[3] = pk2(wv.w, wv.w);
            ulonglong2 xv = *(const ulonglong2*)&Xs[k][m0];
#pragma unroll
            for (int i = 0; i < 4; i++) { fma2(acc[i][0], ww[i], xv.x); fma2(acc[i][1], ww[i], xv.y); }
        }
    }
    float vals[4][4];  // [oc i][m j]
#pragma unroll
    for (int i = 0; i < 4; i++) {
        int oc = oc0 + i;
        float al = cs[oc] * rsqrtf(cv[oc] + EPSV);
        float bc = (cb[oc] - cm[oc]) * al + ct[oc];
        float2 v0 = upk(acc[i][0]);
        float2 v1 = upk(acc[i][1]);
        vals[i][0] = fmaxf(v0.x * al + bc, 0.f);
        vals[i][1] = fmaxf(v0.y * al + bc, 0.f);
        vals[i][2] = fmaxf(v1.x * al + bc, 0.f);
        vals[i][3] = fmaxf(v1.y * al + bc, 0.f);
    }
    __nv_bfloat16* gout = d_Ght + (size_t)b * 131072 + (size_t)(pos0 + m0) * 32 + oc0;
#pragma unroll
    for (int j = 0; j < 4; j++) {
        __nv_bfloat162 lo = __floats2bfloat162_rn(vals[0][j], vals[1][j]);
        __nv_bfloat162 hi = __floats2bfloat162_rn(vals[2][j], vals[3][j]);
        uint2 u;
        u.x = *(unsigned*)&lo;
        u.y = *(unsigned*)&hi;
        *(uint2*)(gout + j * 32) = u;
    }
}

// ---------------------------------------------------------------------------
// conv3: 1x1 conv (256->128) + BN + ReLU + 2x2 maxpool -> d_Hh[b][c][n] (bf16)
// ---------------------------------------------------------------------------
__global__ void __launch_bounds__(256) conv3_kernel(
    const float* __restrict__ x, const float* __restrict__ w,
    const float* __restrict__ cb, const float* __restrict__ cs,
    const float* __restrict__ ct, const float* __restrict__ cm,
    const float* __restrict__ cv)
{
    int b = blockIdx.y;
    int r = blockIdx.x;
    int t = threadIdx.x;
    int og = t >> 4, mg = t & 15;
    int oc0 = og * 8;
    int m0a = mg * 4;

    __shared__ float Xs[32][128];
    __shared__ float Ws[32][128];

    const float* xb = x + (size_t)b * 256 * 4096 + (size_t)r * 128;

    unsigned long long aa[8][2], ab[8][2];
#pragma unroll
    for (int i = 0; i < 8; i++) { aa[i][0] = aa[i][1] = 0ull; ab[i][0] = ab[i][1] = 0ull; }

    for (int kc = 0; kc < 256; kc += 32) {
        __syncthreads();
        for (int i = t; i < 32 * 128; i += 256) {
            int k = i >> 7, mm = i & 127;
            Xs[k][mm] = xb[(size_t)(kc + k) * 4096 + mm];
        }
        for (int i = t; i < 32 * 128; i += 256) {
            int oc = i >> 5, k = i & 31;
            Ws[k][oc] = w[oc * 256 + kc + k];
        }
        __syncthreads();
#pragma unroll
        for (int k = 0; k < 32; k++) {
            float wr[8];
            *(float4*)&wr[0] = *(const float4*)&Ws[k][oc0];
            *(float4*)&wr[4] = *(const float4*)&Ws[k][oc0 + 4];
            unsigned long long ww[8];
#pragma unroll
            for (int i = 0; i < 8; i++) ww[i] = pk2(wr[i], wr[i]);
            ulonglong2 xa = *(const ulonglong2*)&Xs[k][m0a];
            ulonglong2 xv2 = *(const ulonglong2*)&Xs[k][m0a + 64];
#pragma unroll
            for (int i = 0; i < 8; i++) {
                fma2(aa[i][0], ww[i], xa.x);  fma2(aa[i][1], ww[i], xa.y);
                fma2(ab[i][0], ww[i], xv2.x); fma2(ab[i][1], ww[i], xv2.y);
            }
        }
    }
#pragma unroll
    for (int i = 0; i < 8; i++) {
        int oc = oc0 + i;
        float al = cs[oc] * rsqrtf(cv[oc] + EPSV);
        float bc = (cb[oc] - cm[oc]) * al + ct[oc];
        float2 a0 = upk(aa[i][0]), a1 = upk(aa[i][1]);
        float2 b0 = upk(ab[i][0]), b1 = upk(ab[i][1]);
        float va0 = fmaxf(a0.x * al + bc, 0.f), va1 = fmaxf(a0.y * al + bc, 0.f);
        float va2 = fmaxf(a1.x * al + bc, 0.f), va3 = fmaxf(a1.y * al + bc, 0.f);
        float vb0 = fmaxf(b0.x * al + bc, 0.f), vb1 = fmaxf(b0.y * al + bc, 0.f);
        float vb2 = fmaxf(b1.x * al + bc, 0.f), vb3 = fmaxf(b1.y * al + bc, 0.f);
        float p0 = fmaxf(fmaxf(va0, va1), fmaxf(vb0, vb1));
        float p1 = fmaxf(fmaxf(va2, va3), fmaxf(vb2, vb3));
        __nv_bfloat162 hp = __floats2bfloat162_rn(p0, p1);
        *(__nv_bfloat162*)(d_Hh + (size_t)b * 131072 + (size_t)oc * 1024 + r * 32 + mg * 2) = hp;
    }
}

// ---------------------------------------------------------------------------
// Fused flash attention with bf16 tensor-core mma (m16n8k16).
// Block: 64 m x 128 c, n-chunks of 64. 8 warps.
// GEMM1 warps: (wid>>1) -> n quarter (16), (wid&1) -> m half (32).
// GEMM2 warps: (wid>>1) -> c quarter (32), (wid&1) -> m half (32).
// Softmax (over n) via in-register shuffles + small smem reductions.
// ---------------------------------------------------------------------------
__global__ void __launch_bounds__(256) attn_kernel()
{
    const int b = blockIdx.y;
    const int m0 = blockIdx.x * 64;
    const int t = threadIdx.x;
    const int lane = t & 31, wid = t >> 5;
    const int g = lane >> 2, t4 = lane & 3;

    __shared__ __align__(16) __nv_bfloat16 Gs[64 * 40];   // [m][k] stride 40
    __shared__ __align__(16) __nv_bfloat16 Fs[64 * 40];   // [n][k] stride 40
    __shared__ __align__(16) __nv_bfloat16 Hs[128 * 72];  // [c][n] stride 72
    __shared__ __align__(16) __nv_bfloat16 Ps[64 * 72];   // [m][n] stride 72
    __shared__ float RowM[64], RowS[64], RowScale[64];
    __shared__ float Red[4][64];

    const __nv_bfloat16* gB = d_Ght + (size_t)b * 131072;
    const __nv_bfloat16* fB = d_Fh + (size_t)b * 32768;
    const __nv_bfloat16* hB = d_Hh + (size_t)b * 131072;

    {   // load G tile once (already [m][k] in global)
        int m = t >> 2, kq = (t & 3) * 8;
        *(float4*)&Gs[m * 40 + kq] = *(const float4*)(gB + (size_t)(m0 + m) * 32 + kq);
    }
    if (t < 64) { RowM[t] = -1e30f; RowS[t] = 0.f; }

    const int w_n  = (wid >> 1) * 16;
    const int w_m1 = (wid & 1) * 32;
    const int w_c  = (wid >> 1) * 32;
    const int w_m2 = (wid & 1) * 32;
    const int rrow = wid >> 1;

    float o[2][4][4];
#pragma unroll
    for (int i = 0; i < 2; i++)
#pragma unroll
        for (int j = 0; j < 4; j++)
#pragma unroll
            for (int e = 0; e < 4; e++) o[i][j][e] = 0.f;

    for (int n0 = 0; n0 < 1024; n0 += 64) {
        __syncthreads();
        {   // F chunk [n][k]
            int n = t >> 2, kq = (t & 3) * 8;
            *(float4*)&Fs[n * 40 + kq] = *(const float4*)(fB + (size_t)(n0 + n) * 32 + kq);
        }
        {   // H chunk [c][n]
            int c = t >> 1, nq = (t & 1) * 32;
            const __nv_bfloat16* src = hB + (size_t)c * 1024 + n0 + nq;
            float4 v0 = *(const float4*)(src);
            float4 v1 = *(const float4*)(src + 8);
            float4 v2 = *(const float4*)(src + 16);
            float4 v3 = *(const float4*)(src + 24);
            *(float4*)&Hs[c * 72 + nq]      = v0;
            *(float4*)&Hs[c * 72 + nq + 8]  = v1;
            *(float4*)&Hs[c * 72 + nq + 16] = v2;
            *(float4*)&Hs[c * 72 + nq + 24] = v3;
        }
        __syncthreads();

        // ---- GEMM1: S[16n x 32m] per warp ----
        float sc[4][4];
#pragma unroll
        for (int mt = 0; mt < 4; mt++)
#pragma unroll
            for (int e = 0; e < 4; e++) sc[mt][e] = 0.f;

#pragma unroll
        for (int ks = 0; ks < 2; ks++) {
            int k0 = ks * 16;
            unsigned a0 = *(const unsigned*)&Fs[(w_n + g) * 40 + k0 + 2 * t4];
            unsigned a1 = *(const unsigned*)&Fs[(w_n + g + 8) * 40 + k0 + 2 * t4];
            unsigned a2 = *(const unsigned*)&Fs[(w_n + g) * 40 + k0 + 8 + 2 * t4];
            unsigned a3 = *(const unsigned*)&Fs[(w_n + g + 8) * 40 + k0 + 8 + 2 * t4];
#pragma unroll
            for (int mt = 0; mt < 4; mt++) {
                int mr = w_m1 + mt * 8 + g;
                unsigned b0 = *(const unsigned*)&Gs[mr * 40 + k0 + 2 * t4];
                unsigned b1 = *(const unsigned*)&Gs[mr * 40 + k0 + 8 + 2 * t4];
                mma_bf16(sc[mt], a0, a1, a2, a3, b0, b1);
            }
        }

        // ---- chunk max per m-column (reduce over n) ----
#pragma unroll
        for (int mt = 0; mt < 4; mt++) {
            float mA = fmaxf(sc[mt][0], sc[mt][2]);
            float mB = fmaxf(sc[mt][1], sc[mt][3]);
#pragma unroll
            for (int off = 4; off < 32; off <<= 1) {
                mA = fmaxf(mA, __shfl_xor_sync(0xffffffffu, mA, off));
                mB = fmaxf(mB, __shfl_xor_sync(0xffffffffu, mB, off));
            }
            if (lane < 4) {
                Red[rrow][w_m1 + mt * 8 + 2 * t4]     = mA;
                Red[rrow][w_m1 + mt * 8 + 2 * t4 + 1] = mB;
            }
        }
        __syncthreads();
        if (t < 64) {
            float mx = fmaxf(fmaxf(Red[0][t], Red[1][t]), fmaxf(Red[2][t], Red[3][t]));
            float om = RowM[t];
            float nm = fmaxf(om, mx);
            RowScale[t] = __expf(om - nm);
            RowM[t] = nm;
        }
        __syncthreads();

        // ---- exp + write P (bf16, [m][n]) + column sums ----
#pragma unroll
        for (int mt = 0; mt < 4; mt++) {
            int col = w_m1 + mt * 8 + 2 * t4;
            float rm0 = RowM[col], rm1 = RowM[col + 1];
            float p0 = __expf(sc[mt][0] - rm0);
            float p1 = __expf(sc[mt][1] - rm1);
            float p2 = __expf(sc[mt][2] - rm0);
            float p3 = __expf(sc[mt][3] - rm1);
            Ps[col * 72 + w_n + g]           = __float2bfloat16_rn(p0);
            Ps[(col + 1) * 72 + w_n + g]     = __float2bfloat16_rn(p1);
            Ps[col * 72 + w_n + g + 8]       = __float2bfloat16_rn(p2);
            Ps[(col + 1) * 72 + w_n + g + 8] = __float2bfloat16_rn(p3);
            float sA = p0 + p2, sB = p1 + p3;
#pragma unroll
            for (int off = 4; off < 32; off <<= 1) {
                sA += __shfl_xor_sync(0xffffffffu, sA, off);
                sB += __shfl_xor_sync(0xffffffffu, sB, off);
            }
            if (lane < 4) {
                Red[rrow][col]     = sA;
                Red[rrow][col + 1] = sB;
            }
        }

        // ---- rescale O accumulators by per-column scale ----
#pragma unroll
        for (int nt = 0; nt < 4; nt++) {
            float s0 = RowScale[w_m2 + nt * 8 + 2 * t4];
            float s1 = RowScale[w_m2 + nt * 8 + 2 * t4 + 1];
#pragma unroll
            for (int mt = 0; mt < 2; mt++) {
                o[mt][nt][0] *= s0; o[mt][nt][1] *= s1;
                o[mt][nt][2] *= s0; o[mt][nt][3] *= s1;
            }
        }
        __syncthreads();
        if (t < 64)
            RowS[t] = RowS[t] * RowScale[t] +
                      (Red[0][t] + Red[1][t] + Red[2][t] + Red[3][t]);

        // ---- GEMM2: O[32c x 32m] per warp += H . P ----
#pragma unroll
        for (int ks = 0; ks < 4; ks++) {
            int k0 = ks * 16;
            unsigned a[2][4];
#pragma unroll
            for (int mt = 0; mt < 2; mt++) {
                int cr = w_c + mt * 16;
                a[mt][0] = *(const unsigned*)&Hs[(cr + g) * 72 + k0 + 2 * t4];
                a[mt][1] = *(const unsigned*)&Hs[(cr + g + 8) * 72 + k0 + 2 * t4];
                a[mt][2] = *(const unsigned*)&Hs[(cr + g) * 72 + k0 + 8 + 2 * t4];
                a[mt][3] = *(const unsigned*)&Hs[(cr + g + 8) * 72 + k0 + 8 + 2 * t4];
            }
#pragma unroll
            for (int nt = 0; nt < 4; nt++) {
                int mr = w_m2 + nt * 8 + g;
                unsigned b0 = *(const unsigned*)&Ps[mr * 72 + k0 + 2 * t4];
                unsigned b1 = *(const unsigned*)&Ps[mr * 72 + k0 + 8 + 2 * t4];
                mma_bf16(o[0][nt], a[0][0], a[0][1], a[0][2], a[0][3], b0, b1);
                mma_bf16(o[1][nt], a[1][0], a[1][1], a[1][2], a[1][3], b0, b1);
            }
        }
    }
    __syncthreads();

    // ---- normalize + store ----
    float* oB = d_O + (size_t)b * 524288 + m0;
#pragma unroll
    for (int nt = 0; nt < 4; nt++) {
        int mc = w_m2 + nt * 8 + 2 * t4;
        float i0 = 1.f / RowS[mc];
        float i1 = 1.f / RowS[mc + 1];
#pragma unroll
        for (int mt = 0; mt < 2; mt++) {
            int cr = w_c + mt * 16 + g;
            oB[(size_t)cr * 4096 + mc]           = o[mt][nt][0] * i0;
            oB[(size_t)cr * 4096 + mc + 1]       = o[mt][nt][1] * i1;
            oB[(size_t)(cr + 8) * 4096 + mc]     = o[mt][nt][2] * i0;
            oB[(size_t)(cr + 8) * 4096 + mc + 1] = o[mt][nt][3] * i1;
        }
    }
}

// ---------------------------------------------------------------------------
// conv4: 1x1 conv (128->256) + BN (no ReLU), out = gamma*bn + x
// ---------------------------------------------------------------------------
__global__ void __launch_bounds__(256) conv4_kernel(
    const float* __restrict__ x, const float* __restrict__ w,
    const float* __restrict__ cb, const float* __restrict__ cs,
    const float* __restrict__ ct, const float* __restrict__ cm,
    const float* __restrict__ cv, const float* __restrict__ gamma,
    float* __restrict__ out)
{
    int b = blockIdx.z;
    int OC0 = blockIdx.y * 64;
    int pos0 = blockIdx.x * 128;
    int t = threadIdx.x;
    int og = t >> 4, mg = t & 15;
    int oc0l = og * 4;
    int m0a = mg * 4;

    __shared__ float Xs[32][128];
    __shared__ float Ws[32][64];

    const float* ob = d_O + (size_t)b * 524288 + pos0;

    unsigned long long aa[4][2], ab[4][2];
#pragma unroll
    for (int i = 0; i < 4; i++) { aa[i][0] = aa[i][1] = 0ull; ab[i][0] = ab[i][1] = 0ull; }

    for (int kc = 0; kc < 128; kc += 32) {
        __syncthreads();
        for (int i = t; i < 32 * 128; i += 256) {
            int k = i >> 7, mm = i & 127;
            Xs[k][mm] = ob[(size_t)(kc + k) * 4096 + mm];
        }
        for (int i = t; i < 32 * 64; i += 256) {
            int oc = i >> 5, k = i & 31;
            Ws[k][oc] = w[(OC0 + oc) * 128 + kc + k];
        }
        __syncthreads();
#pragma unroll
        for (int k = 0; k < 32; k++) {
            float4 wv = *(const float4*)&Ws[k][oc0l];
            unsigned long long ww[4];
            ww[0] = pk2(wv.x, wv.x); ww[1] = pk2(wv.y, wv.y);
            ww[2] = pk2(wv.z, wv.z); ww[3] = pk2(wv.w, wv.w);
            ulonglong2 xa = *(const ulonglong2*)&Xs[k][m0a];
            ulonglong2 xv2 = *(const ulonglong2*)&Xs[k][m0a + 64];
#pragma unroll
            for (int i = 0; i < 4; i++) {
                fma2(aa[i][0], ww[i], xa.x);  fma2(aa[i][1], ww[i], xa.y);
                fma2(ab[i][0], ww[i], xv2.x); fma2(ab[i][1], ww[i], xv2.y);
            }
        }
    }
    float gm = *gamma;
#pragma unroll
    for (int i = 0; i < 4; i++) {
        int oc = OC0 + oc0l + i;
        float al = cs[oc] * rsqrtf(cv[oc] + EPSV);
        float bc = (cb[oc] - cm[oc]) * al + ct[oc];
        size_t base = (size_t)b * 1048576 + (size_t)oc * 4096 + pos0;

        float2 a0 = upk(aa[i][0]), a1 = upk(aa[i][1]);
        float4 xv = *(const float4*)(x + base + m0a);
        float4 r4;
        r4.x = gm * (a0.x * al + bc) + xv.x;
        r4.y = gm * (a0.y * al + bc) + xv.y;
        r4.z = gm * (a1.x * al + bc) + xv.z;
        r4.w = gm * (a1.y * al + bc) + xv.w;
        *(float4*)(out + base + m0a) = r4;

        float2 b0 = upk(ab[i][0]), b1 = upk(ab[i][1]);
        float4 xw = *(const float4*)(x + base + m0a + 64);
        float4 s4;
        s4.x = gm * (b0.x * al + bc) + xw.x;
        s4.y = gm * (b0.y * al + bc) + xw.y;
        s4.z = gm * (b1.x * al + bc) + xw.z;
        s4.w = gm * (b1.y * al + bc) + xw.w;
        *(float4*)(out + base + m0a + 64) = s4;
    }
}

// ---------------------------------------------------------------------------
extern "C" void kernel_launch(void* const* d_in, const int* in_sizes, int n_in,
                              void* d_out, int out_size)
{
    const float* x = (const float*)d_in[0];
    const float* w1 = (const float*)d_in[1];
    const float* b1 = (const float*)d_in[2];
    const float* s1 = (const float*)d_in[3];
    const float* t1 = (const float*)d_in[4];
    const float* m1 = (const float*)d_in[5];
    const float* v1 = (const float*)d_in[6];
    const float* w2 = (const float*)d_in[7];
    const float* b2 = (const float*)d_in[8];
    const float* s2 = (const float*)d_in[9];
    const float* t2 = (const float*)d_in[10];
    const float* m2 = (const float*)d_in[11];
    const float* v2 = (const float*)d_in[12];
    const float* w3 = (const float*)d_in[13];
    const float* b3 = (const float*)d_in[14];
    const float* s3 = (const float*)d_in[15];
    const float* t3 = (const float*)d_in[16];
    const float* m3 = (const float*)d_in[17];
    const float* v3 = (const float*)d_in[18];
    const float* w4 = (const float*)d_in[19];
    const float* b4 = (const float*)d_in[20];
    const float* s4 = (const float*)d_in[21];
    const float* t4 = (const float*)d_in[22];
    const float* m4 = (const float*)d_in[23];
    const float* v4 = (const float*)d_in[24];
    const float* gamma = (const float*)d_in[25];

    conv1_kernel<<<dim3(32, 8), 256>>>(x, w1, b1, s1, t1, m1, v1);
    conv2_kernel<<<dim3(32, 8), 256>>>(x, w2, b2, s2, t2, m2, v2);
    conv3_kernel<<<dim3(32, 8), 256>>>(x, w3, b3, s3, t3, m3, v3);
    attn_kernel<<<dim3(64, 8), 256>>>();
    conv4_kernel<<<dim3(32, 4, 8), 256>>>(x, w4, b4, s4, t4, m4, v4, gamma,
                                          (float*)d_out);
}

// round 9
// speedup vs baseline: 4.8806x; 2.3778x over previous
#include <cuda_runtime.h>
#include <cuda_bf16.h>

#define EPSV 1e-5f

// ---------------- scratch (device globals; no cudaMalloc allowed) ----------
__device__ __nv_bfloat16 d_Fh[8 * 1024 * 32];    // f:  [b][n=1024][k=32]
__device__ __nv_bfloat16 d_Ght[8 * 4096 * 32];   // g^T:[b][m=4096][k=32]
__device__ __nv_bfloat16 d_Hh[8 * 128 * 1024];   // hh: [b][c=128][n=1024]
__device__ float d_O[8 * 128 * 4096];            // o:  [b][c=128][m=4096]

__device__ __nv_bfloat16 d_Wc[192 * 256];        // BN-folded W for conv1|2|3 (oc-major)
__device__ float d_Bc[192];                      // folded biases conv1|2|3
__device__ __nv_bfloat16 d_W4h[256 * 128];       // BN-folded W4
__device__ float d_B4[256];                      // folded bias conv4

// ---------------- mma / ldmatrix helpers ------------------------------------
__device__ __forceinline__ void mma_bf16(float c[4], unsigned a0, unsigned a1,
                                         unsigned a2, unsigned a3,
                                         unsigned b0, unsigned b1) {
    asm volatile(
        "mma.sync.aligned.m16n8k16.row.col.f32.bf16.bf16.f32 "
        "{%0,%1,%2,%3}, {%4,%5,%6,%7}, {%8,%9}, {%0,%1,%2,%3};"
        : "+f"(c[0]), "+f"(c[1]), "+f"(c[2]), "+f"(c[3])
        : "r"(a0), "r"(a1), "r"(a2), "r"(a3), "r"(b0), "r"(b1));
}
__device__ __forceinline__ unsigned smem_u32(const void* p) {
    return (unsigned)__cvta_generic_to_shared(p);
}
__device__ __forceinline__ void ldsm_x4(unsigned& r0, unsigned& r1, unsigned& r2,
                                        unsigned& r3, unsigned addr) {
    asm volatile("ldmatrix.sync.aligned.m8n8.x4.shared.b16 {%0,%1,%2,%3}, [%4];"
                 : "=r"(r0), "=r"(r1), "=r"(r2), "=r"(r3) : "r"(addr));
}
__device__ __forceinline__ void ldsm_x2t(unsigned& r0, unsigned& r1, unsigned addr) {
    asm volatile("ldmatrix.sync.aligned.m8n8.x2.trans.shared.b16 {%0,%1}, [%2];"
                 : "=r"(r0), "=r"(r1) : "r"(addr));
}
__device__ __forceinline__ unsigned bf2u(float a, float b) {
    __nv_bfloat162 h = __floats2bfloat162_rn(a, b);
    return *(unsigned*)&h;
}

// ---------------------------------------------------------------------------
// prep: fold BN into weights (bf16) and biases (fp32)
// ---------------------------------------------------------------------------
__global__ void __launch_bounds__(256) prep_kernel(
    const float* __restrict__ w1, const float* __restrict__ b1,
    const float* __restrict__ s1, const float* __restrict__ t1,
    const float* __restrict__ m1, const float* __restrict__ v1,
    const float* __restrict__ w2, const float* __restrict__ b2,
    const float* __restrict__ s2, const float* __restrict__ t2,
    const float* __restrict__ m2, const float* __restrict__ v2,
    const float* __restrict__ w3, const float* __restrict__ b3,
    const float* __restrict__ s3, const float* __restrict__ t3,
    const float* __restrict__ m3, const float* __restrict__ v3,
    const float* __restrict__ w4, const float* __restrict__ b4,
    const float* __restrict__ s4, const float* __restrict__ t4,
    const float* __restrict__ m4, const float* __restrict__ v4)
{
    int gid = blockIdx.x * 256 + threadIdx.x;
    int stride = gridDim.x * 256;

    // biases
    if (gid < 192) {
        int oc = gid;
        float al, bb;
        if (oc < 32) {
            al = s1[oc] * rsqrtf(v1[oc] + EPSV);
            bb = (b1[oc] - m1[oc]) * al + t1[oc];
        } else if (oc < 64) {
            int o = oc - 32;
            al = s2[o] * rsqrtf(v2[o] + EPSV);
            bb = (b2[o] - m2[o]) * al + t2[o];
        } else {
            int o = oc - 64;
            al = s3[o] * rsqrtf(v3[o] + EPSV);
            bb = (b3[o] - m3[o]) * al + t3[o];
        }
        d_Bc[oc] = bb;
    } else if (gid < 448) {
        int oc = gid - 192;
        float al = s4[oc] * rsqrtf(v4[oc] + EPSV);
        d_B4[oc] = (b4[oc] - m4[oc]) * al + t4[oc];
    }

    // folded weights conv1|2|3: [192][256]
    for (int j = gid; j < 192 * 256; j += stride) {
        int oc = j >> 8, k = j & 255;
        float wv, al;
        if (oc < 32) {
            al = s1[oc] * rsqrtf(v1[oc] + EPSV);
            wv = w1[oc * 256 + k];
        } else if (oc < 64) {
            int o = oc - 32;
            al = s2[o] * rsqrtf(v2[o] + EPSV);
            wv = w2[o * 256 + k];
        } else {
            int o = oc - 64;
            al = s3[o] * rsqrtf(v3[o] + EPSV);
            wv = w3[o * 256 + k];
        }
        d_Wc[j] = __float2bfloat16_rn(wv * al);
    }
    // folded conv4 weights: [256][128]
    for (int j = gid; j < 256 * 128; j += stride) {
        int oc = j >> 7;
        float al = s4[oc] * rsqrtf(v4[oc] + EPSV);
        d_W4h[j] = __float2bfloat16_rn(w4[j] * al);
    }
}

// ---------------------------------------------------------------------------
// Fused conv1+2+3 via tensor cores.
// Block: 512 threads (16 warps), r = row-pair (128 spatial m), C[192 oc][128 m].
// Warp tile 48 oc x 32 m (warps: oc group = wid&3, m group = wid>>2).
// Epilogues: oc 0-31 -> pool -> d_Fh; 32-63 -> transpose -> d_Ght; 64-191 -> pool -> d_Hh.
// ---------------------------------------------------------------------------
__global__ void __launch_bounds__(512) conv123_kernel(const float* __restrict__ x)
{
    __shared__ __align__(16) char sm[45056];
    __nv_bfloat16* Xs = (__nv_bfloat16*)sm;             // [64][136]
    __nv_bfloat16* Ws = (__nv_bfloat16*)(sm + 17408);   // [192][72]
    __nv_bfloat16* HP1 = (__nv_bfloat16*)sm;            // [32][64]  (epilogue)
    __nv_bfloat16* HP3 = (__nv_bfloat16*)(sm + 4096);   // [128][64] (epilogue)
    __nv_bfloat16* Gt  = (__nv_bfloat16*)(sm + 20480);  // [128][40] (epilogue)

    const int b = blockIdx.y, r = blockIdx.x, t = threadIdx.x;
    const int lane = t & 31, wid = t >> 5;
    const int g = lane >> 2, t4 = lane & 3;
    const int oc0w = (wid & 3) * 48, m0w = (wid >> 2) * 32;

    const float* xb = x + (size_t)b * 1048576 + (size_t)r * 128;

    float c[3][4][4];
#pragma unroll
    for (int i = 0; i < 3; i++)
#pragma unroll
        for (int j = 0; j < 4; j++)
#pragma unroll
            for (int e = 0; e < 4; e++) c[i][j][e] = 0.f;

    for (int kc = 0; kc < 256; kc += 64) {
        __syncthreads();
        // stage X chunk: 64 k-rows x 128 m, fp32 -> bf16
#pragma unroll
        for (int j = 0; j < 4; j++) {
            int i = t + j * 512;
            int row = i >> 5, col4 = i & 31;
            float4 v = *(const float4*)(xb + (size_t)(kc + row) * 4096 + col4 * 4);
            uint2 u;
            u.x = bf2u(v.x, v.y);
            u.y = bf2u(v.z, v.w);
            *(uint2*)(Xs + row * 136 + col4 * 4) = u;
        }
        // stage W chunk: 192 oc x 64 k (bf16 already)
#pragma unroll
        for (int j = 0; j < 3; j++) {
            int i = t + j * 512;
            int row = i >> 3, part = i & 7;
            *(uint4*)(Ws + row * 72 + part * 8) =
                *(const uint4*)(d_Wc + row * 256 + kc + part * 8);
        }
        __syncthreads();

#pragma unroll
        for (int ks = 0; ks < 4; ks++) {
            int k0 = ks * 16;
            unsigned a[3][4];
#pragma unroll
            for (int mt = 0; mt < 3; mt++) {
                unsigned addr = smem_u32(Ws + (oc0w + mt * 16 + (lane & 15)) * 72 +
                                         k0 + ((lane >> 4) << 3));
                ldsm_x4(a[mt][0], a[mt][1], a[mt][2], a[mt][3], addr);
            }
#pragma unroll
            for (int nt = 0; nt < 4; nt++) {
                unsigned b0, b1;
                unsigned addr = smem_u32(Xs + (k0 + (lane & 15)) * 136 + m0w + nt * 8);
                ldsm_x2t(b0, b1, addr);
#pragma unroll
                for (int mt = 0; mt < 3; mt++)
                    mma_bf16(c[mt][nt], a[mt][0], a[mt][1], a[mt][2], a[mt][3], b0, b1);
            }
        }
    }
    __syncthreads();

    // ---- epilogue: route fragments ----
#pragma unroll
    for (int mt = 0; mt < 3; mt++) {
        int ocb = oc0w + mt * 16;
        float bg  = d_Bc[ocb + g];
        float bg8 = d_Bc[ocb + 8 + g];
#pragma unroll
        for (int nt = 0; nt < 4; nt++) {
            int mloc = m0w + nt * 8 + 2 * t4;
            int rh = mloc >> 6, cp = (mloc & 63) >> 1;
            float v0 = fmaxf(c[mt][nt][0] + bg, 0.f);
            float v1 = fmaxf(c[mt][nt][1] + bg, 0.f);
            float v2 = fmaxf(c[mt][nt][2] + bg8, 0.f);
            float v3 = fmaxf(c[mt][nt][3] + bg8, 0.f);
            if (ocb < 32) {
                HP1[(ocb + g) * 64 + rh * 32 + cp]     = __float2bfloat16_rn(fmaxf(v0, v1));
                HP1[(ocb + 8 + g) * 64 + rh * 32 + cp] = __float2bfloat16_rn(fmaxf(v2, v3));
            } else if (ocb < 64) {
                int oc = ocb - 32 + g;
                Gt[mloc * 40 + oc]           = __float2bfloat16_rn(v0);
                Gt[(mloc + 1) * 40 + oc]     = __float2bfloat16_rn(v1);
                Gt[mloc * 40 + oc + 8]       = __float2bfloat16_rn(v2);
                Gt[(mloc + 1) * 40 + oc + 8] = __float2bfloat16_rn(v3);
            } else {
                HP3[(ocb - 64 + g) * 64 + rh * 32 + cp]     = __float2bfloat16_rn(fmaxf(v0, v1));
                HP3[(ocb - 64 + 8 + g) * 64 + rh * 32 + cp] = __float2bfloat16_rn(fmaxf(v2, v3));
            }
        }
    }
    __syncthreads();

    // ---- outputs ----
    {   // d_Fh: 32 n x 32 oc
        int cp = t >> 4, oc0 = (t & 15) * 2;
        float f0 = __bfloat162float(__hmax(HP1[oc0 * 64 + cp], HP1[oc0 * 64 + 32 + cp]));
        float f1 = __bfloat162float(__hmax(HP1[(oc0 + 1) * 64 + cp], HP1[(oc0 + 1) * 64 + 32 + cp]));
        __nv_bfloat162 h = __floats2bfloat162_rn(f0, f1);
        *(__nv_bfloat162*)(d_Fh + (size_t)b * 32768 + (size_t)(r * 32 + cp) * 32 + oc0) = h;
    }
    {   // d_Hh: 128 c x 32 n
        int cc = t >> 2, q = (t & 3) * 8;
        __nv_bfloat16 out8[8];
#pragma unroll
        for (int jj = 0; jj < 8; jj++)
            out8[jj] = __hmax(HP3[cc * 64 + q + jj], HP3[cc * 64 + 32 + q + jj]);
        *(uint4*)(d_Hh + (size_t)b * 131072 + (size_t)cc * 1024 + r * 32 + q) =
            *(uint4*)out8;
    }
    {   // d_Ght: 128 m x 32 k
        int row = t >> 2, part = t & 3;
        *(uint4*)(d_Ght + (size_t)b * 131072 + (size_t)(r * 128 + row) * 32 + part * 8) =
            *(uint4*)(Gt + row * 40 + part * 8);
    }
}

// ---------------------------------------------------------------------------
// Fused flash attention with bf16 tensor-core mma (unchanged from R7).
// ---------------------------------------------------------------------------
__global__ void __launch_bounds__(256) attn_kernel()
{
    const int b = blockIdx.y;
    const int m0 = blockIdx.x * 64;
    const int t = threadIdx.x;
    const int lane = t & 31, wid = t >> 5;
    const int g = lane >> 2, t4 = lane & 3;

    __shared__ __align__(16) __nv_bfloat16 Gs[64 * 40];   // [m][k] stride 40
    __shared__ __align__(16) __nv_bfloat16 Fs[64 * 40];   // [n][k] stride 40
    __shared__ __align__(16) __nv_bfloat16 Hs[128 * 72];  // [c][n] stride 72
    __shared__ __align__(16) __nv_bfloat16 Ps[64 * 72];   // [m][n] stride 72
    __shared__ float RowM[64], RowS[64], RowScale[64];
    __shared__ float Red[4][64];

    const __nv_bfloat16* gB = d_Ght + (size_t)b * 131072;
    const __nv_bfloat16* fB = d_Fh + (size_t)b * 32768;
    const __nv_bfloat16* hB = d_Hh + (size_t)b * 131072;

    {   // load G tile once (already [m][k] in global)
        int m = t >> 2, kq = (t & 3) * 8;
        *(float4*)&Gs[m * 40 + kq] = *(const float4*)(gB + (size_t)(m0 + m) * 32 + kq);
    }
    if (t < 64) { RowM[t] = -1e30f; RowS[t] = 0.f; }

    const int w_n  = (wid >> 1) * 16;
    const int w_m1 = (wid & 1) * 32;
    const int w_c  = (wid >> 1) * 32;
    const int w_m2 = (wid & 1) * 32;
    const int rrow = wid >> 1;

    float o[2][4][4];
#pragma unroll
    for (int i = 0; i < 2; i++)
#pragma unroll
        for (int j = 0; j < 4; j++)
#pragma unroll
            for (int e = 0; e < 4; e++) o[i][j][e] = 0.f;

    for (int n0 = 0; n0 < 1024; n0 += 64) {
        __syncthreads();
        {   // F chunk [n][k]
            int n = t >> 2, kq = (t & 3) * 8;
            *(float4*)&Fs[n * 40 + kq] = *(const float4*)(fB + (size_t)(n0 + n) * 32 + kq);
        }
        {   // H chunk [c][n]
            int cpos = t >> 1, nq = (t & 1) * 32;
            const __nv_bfloat16* src = hB + (size_t)cpos * 1024 + n0 + nq;
            float4 v0 = *(const float4*)(src);
            float4 v1 = *(const float4*)(src + 8);
            float4 v2 = *(const float4*)(src + 16);
            float4 v3 = *(const float4*)(src + 24);
            *(float4*)&Hs[cpos * 72 + nq]      = v0;
            *(float4*)&Hs[cpos * 72 + nq + 8]  = v1;
            *(float4*)&Hs[cpos * 72 + nq + 16] = v2;
            *(float4*)&Hs[cpos * 72 + nq + 24] = v3;
        }
        __syncthreads();

        // ---- GEMM1: S[16n x 32m] per warp ----
        float sc[4][4];
#pragma unroll
        for (int mt = 0; mt < 4; mt++)
#pragma unroll
            for (int e = 0; e < 4; e++) sc[mt][e] = 0.f;

#pragma unroll
        for (int ks = 0; ks < 2; ks++) {
            int k0 = ks * 16;
            unsigned a0 = *(const unsigned*)&Fs[(w_n + g) * 40 + k0 + 2 * t4];
            unsigned a1 = *(const unsigned*)&Fs[(w_n + g + 8) * 40 + k0 + 2 * t4];
            unsigned a2 = *(const unsigned*)&Fs[(w_n + g) * 40 + k0 + 8 + 2 * t4];
            unsigned a3 = *(const unsigned*)&Fs[(w_n + g + 8) * 40 + k0 + 8 + 2 * t4];
#pragma unroll
            for (int mt = 0; mt < 4; mt++) {
                int mr = w_m1 + mt * 8 + g;
                unsigned b0 = *(const unsigned*)&Gs[mr * 40 + k0 + 2 * t4];
                unsigned b1 = *(const unsigned*)&Gs[mr * 40 + k0 + 8 + 2 * t4];
                mma_bf16(sc[mt], a0, a1, a2, a3, b0, b1);
            }
        }

        // ---- chunk max per m-column (reduce over n) ----
#pragma unroll
        for (int mt = 0; mt < 4; mt++) {
            float mA = fmaxf(sc[mt][0], sc[mt][2]);
            float mB = fmaxf(sc[mt][1], sc[mt][3]);
#pragma unroll
            for (int off = 4; off < 32; off <<= 1) {
                mA = fmaxf(mA, __shfl_xor_sync(0xffffffffu, mA, off));
                mB = fmaxf(mB, __shfl_xor_sync(0xffffffffu, mB, off));
            }
            if (lane < 4) {
                Red[rrow][w_m1 + mt * 8 + 2 * t4]     = mA;
                Red[rrow][w_m1 + mt * 8 + 2 * t4 + 1] = mB;
            }
        }
        __syncthreads();
        if (t < 64) {
            float mx = fmaxf(fmaxf(Red[0][t], Red[1][t]), fmaxf(Red[2][t], Red[3][t]));
            float om = RowM[t];
            float nm = fmaxf(om, mx);
            RowScale[t] = __expf(om - nm);
            RowM[t] = nm;
        }
        __syncthreads();

        // ---- exp + write P (bf16, [m][n]) + column sums ----
#pragma unroll
        for (int mt = 0; mt < 4; mt++) {
            int col = w_m1 + mt * 8 + 2 * t4;
            float rm0 = RowM[col], rm1 = RowM[col + 1];
            float p0 = __expf(sc[mt][0] - rm0);
            float p1 = __expf(sc[mt][1] - rm1);
            float p2 = __expf(sc[mt][2] - rm0);
            float p3 = __expf(sc[mt][3] - rm1);
            Ps[col * 72 + w_n + g]           = __float2bfloat16_rn(p0);
            Ps[(col + 1) * 72 + w_n + g]     = __float2bfloat16_rn(p1);
            Ps[col * 72 + w_n + g + 8]       = __float2bfloat16_rn(p2);
            Ps[(col + 1) * 72 + w_n + g + 8] = __float2bfloat16_rn(p3);
            float sA = p0 + p2, sB = p1 + p3;
#pragma unroll
            for (int off = 4; off < 32; off <<= 1) {
                sA += __shfl_xor_sync(0xffffffffu, sA, off);
                sB += __shfl_xor_sync(0xffffffffu, sB, off);
            }
            if (lane < 4) {
                Red[rrow][col]     = sA;
                Red[rrow][col + 1] = sB;
            }
        }

        // ---- rescale O accumulators by per-column scale ----
#pragma unroll
        for (int nt = 0; nt < 4; nt++) {
            float s0 = RowScale[w_m2 + nt * 8 + 2 * t4];
            float s1 = RowScale[w_m2 + nt * 8 + 2 * t4 + 1];
#pragma unroll
            for (int mt = 0; mt < 2; mt++) {
                o[mt][nt][0] *= s0; o[mt][nt][1] *= s1;
                o[mt][nt][2] *= s0; o[mt][nt][3] *= s1;
            }
        }
        __syncthreads();
        if (t < 64)
            RowS[t] = RowS[t] * RowScale[t] +
                      (Red[0][t] + Red[1][t] + Red[2][t] + Red[3][t]);

        // ---- GEMM2: O[32c x 32m] per warp += H . P ----
#pragma unroll
        for (int ks = 0; ks < 4; ks++) {
            int k0 = ks * 16;
            unsigned a[2][4];
#pragma unroll
            for (int mt = 0; mt < 2; mt++) {
                int cr = w_c + mt * 16;
                a[mt][0] = *(const unsigned*)&Hs[(cr + g) * 72 + k0 + 2 * t4];
                a[mt][1] = *(const unsigned*)&Hs[(cr + g + 8) * 72 + k0 + 2 * t4];
                a[mt][2] = *(const unsigned*)&Hs[(cr + g) * 72 + k0 + 8 + 2 * t4];
                a[mt][3] = *(const unsigned*)&Hs[(cr + g + 8) * 72 + k0 + 8 + 2 * t4];
            }
#pragma unroll
            for (int nt = 0; nt < 4; nt++) {
                int mr = w_m2 + nt * 8 + g;
                unsigned b0 = *(const unsigned*)&Ps[mr * 72 + k0 + 2 * t4];
                unsigned b1 = *(const unsigned*)&Ps[mr * 72 + k0 + 8 + 2 * t4];
                mma_bf16(o[0][nt], a[0][0], a[0][1], a[0][2], a[0][3], b0, b1);
                mma_bf16(o[1][nt], a[1][0], a[1][1], a[1][2], a[1][3], b0, b1);
            }
        }
    }
    __syncthreads();

    // ---- normalize + store ----
    float* oB = d_O + (size_t)b * 524288 + m0;
#pragma unroll
    for (int nt = 0; nt < 4; nt++) {
        int mc = w_m2 + nt * 8 + 2 * t4;
        float i0 = 1.f / RowS[mc];
        float i1 = 1.f / RowS[mc + 1];
#pragma unroll
        for (int mt = 0; mt < 2; mt++) {
            int cr = w_c + mt * 16 + g;
            oB[(size_t)cr * 4096 + mc]           = o[mt][nt][0] * i0;
            oB[(size_t)cr * 4096 + mc + 1]       = o[mt][nt][1] * i1;
            oB[(size_t)(cr + 8) * 4096 + mc]     = o[mt][nt][2] * i0;
            oB[(size_t)(cr + 8) * 4096 + mc + 1] = o[mt][nt][3] * i1;
        }
    }
}

// ---------------------------------------------------------------------------
// conv4 via tensor cores: C[128 oc][128 m] per block, K=128.
// out = gamma*(W4'.O + bias4') + x
// ---------------------------------------------------------------------------
__global__ void __launch_bounds__(256) conv4_kernel(
    const float* __restrict__ x, const float* __restrict__ gamma,
    float* __restrict__ out)
{
    __shared__ __align__(16) char sm[35840];
    __nv_bfloat16* Os  = (__nv_bfloat16*)sm;            // [64][136]
    __nv_bfloat16* W4s = (__nv_bfloat16*)(sm + 17408);  // [128][72]

    const int b = blockIdx.z, OC0 = blockIdx.y * 128, pos0 = blockIdx.x * 128;
    const int t = threadIdx.x;
    const int lane = t & 31, wid = t >> 5;
    const int g = lane >> 2, t4 = lane & 3;
    const int oc0w = (wid & 3) * 32, m0w = (wid >> 2) * 64;

    const float* ob = d_O + (size_t)b * 524288 + pos0;

    float c[2][8][4];
#pragma unroll
    for (int i = 0; i < 2; i++)
#pragma unroll
        for (int j = 0; j < 8; j++)
#pragma unroll
            for (int e = 0; e < 4; e++) c[i][j][e] = 0.f;

    for (int kc = 0; kc < 128; kc += 64) {
        __syncthreads();
        // stage O chunk: 64 c-rows x 128 m fp32 -> bf16
#pragma unroll
        for (int j = 0; j < 8; j++) {
            int i = t + j * 256;
            int row = i >> 5, col4 = i & 31;
            float4 v = *(const float4*)(ob + (size_t)(kc + row) * 4096 + col4 * 4);
            uint2 u;
            u.x = bf2u(v.x, v.y);
            u.y = bf2u(v.z, v.w);
            *(uint2*)(Os + row * 136 + col4 * 4) = u;
        }
        // stage W4 chunk: 128 oc x 64 k
#pragma unroll
        for (int j = 0; j < 4; j++) {
            int i = t + j * 256;
            int row = i >> 3, part = i & 7;
            *(uint4*)(W4s + row * 72 + part * 8) =
                *(const uint4*)(d_W4h + (OC0 + row) * 128 + kc + part * 8);
        }
        __syncthreads();

#pragma unroll
        for (int ks = 0; ks < 4; ks++) {
            int k0 = ks * 16;
            unsigned a[2][4];
#pragma unroll
            for (int mt = 0; mt < 2; mt++) {
                unsigned addr = smem_u32(W4s + (oc0w + mt * 16 + (lane & 15)) * 72 +
                                         k0 + ((lane >> 4) << 3));
                ldsm_x4(a[mt][0], a[mt][1], a[mt][2], a[mt][3], addr);
            }
#pragma unroll
            for (int nt = 0; nt < 8; nt++) {
                unsigned b0, b1;
                unsigned addr = smem_u32(Os + (k0 + (lane & 15)) * 136 + m0w + nt * 8);
                ldsm_x2t(b0, b1, addr);
                mma_bf16(c[0][nt], a[0][0], a[0][1], a[0][2], a[0][3], b0, b1);
                mma_bf16(c[1][nt], a[1][0], a[1][1], a[1][2], a[1][3], b0, b1);
            }
        }
    }

    float gm = *gamma;
#pragma unroll
    for (int mt = 0; mt < 2; mt++) {
        int ocA = OC0 + oc0w + mt * 16 + g;
        int ocB = ocA + 8;
        float bA = d_B4[ocA], bB = d_B4[ocB];
        size_t baseA = (size_t)b * 1048576 + (size_t)ocA * 4096 + pos0 + m0w;
        size_t baseB = (size_t)b * 1048576 + (size_t)ocB * 4096 + pos0 + m0w;
#pragma unroll
        for (int nt = 0; nt < 8; nt++) {
            int moff = nt * 8 + 2 * t4;
            float2 xa = *(const float2*)(x + baseA + moff);
            float2 ra;
            ra.x = gm * (c[mt][nt][0] + bA) + xa.x;
            ra.y = gm * (c[mt][nt][1] + bA) + xa.y;
            *(float2*)(out + baseA + moff) = ra;
            float2 xb = *(const float2*)(x + baseB + moff);
            float2 rb;
            rb.x = gm * (c[mt][nt][2] + bB) + xb.x;
            rb.y = gm * (c[mt][nt][3] + bB) + xb.y;
            *(float2*)(out + baseB + moff) = rb;
        }
    }
}

// ---------------------------------------------------------------------------
extern "C" void kernel_launch(void* const* d_in, const int* in_sizes, int n_in,
                              void* d_out, int out_size)
{
    const float* x = (const float*)d_in[0];
    const float* w1 = (const float*)d_in[1];
    const float* b1 = (const float*)d_in[2];
    const float* s1 = (const float*)d_in[3];
    const float* t1 = (const float*)d_in[4];
    const float* m1 = (const float*)d_in[5];
    const float* v1 = (const float*)d_in[6];
    const float* w2 = (const float*)d_in[7];
    const float* b2 = (const float*)d_in[8];
    const float* s2 = (const float*)d_in[9];
    const float* t2 = (const float*)d_in[10];
    const float* m2 = (const float*)d_in[11];
    const float* v2 = (const float*)d_in[12];
    const float* w3 = (const float*)d_in[13];
    const float* b3 = (const float*)d_in[14];
    const float* s3 = (const float*)d_in[15];
    const float* t3 = (const float*)d_in[16];
    const float* m3 = (const float*)d_in[17];
    const float* v3 = (const float*)d_in[18];
    const float* w4 = (const float*)d_in[19];
    const float* b4 = (const float*)d_in[20];
    const float* s4 = (const float*)d_in[21];
    const float* t4 = (const float*)d_in[22];
    const float* m4 = (const float*)d_in[23];
    const float* v4 = (const float*)d_in[24];
    const float* gamma = (const float*)d_in[25];

    prep_kernel<<<64, 256>>>(w1, b1, s1, t1, m1, v1,
                             w2, b2, s2, t2, m2, v2,
                             w3, b3, s3, t3, m3, v3,
                             w4, b4, s4, t4, m4, v4);
    conv123_kernel<<<dim3(32, 8), 512>>>(x);
    attn_kernel<<<dim3(64, 8), 256>>>();
    conv4_kernel<<<dim3(32, 2, 8), 256>>>(x, gamma, (float*)d_out);
}

// round 10
// speedup vs baseline: 6.9797x; 1.4301x over previous
#include <cuda_runtime.h>
#include <cuda_bf16.h>

#define EPSV 1e-5f

// ---------------- scratch (device globals; no cudaMalloc allowed) ----------
__device__ __nv_bfloat16 d_Fh[8 * 1024 * 32];    // f:  [b][n=1024][k=32]
__device__ __nv_bfloat16 d_Ght[8 * 4096 * 32];   // g^T:[b][m=4096][k=32]
__device__ __nv_bfloat16 d_Hh[8 * 128 * 1024];   // hh: [b][c=128][n=1024]
__device__ __nv_bfloat16 d_Ot[8 * 4096 * 128];   // o^T:[b][m=4096][c=128] (bf16)

__device__ __nv_bfloat16 d_Wc[192 * 256];        // BN-folded W for conv1|2|3 (oc-major)
__device__ float d_Bc[192];                      // folded biases conv1|2|3
__device__ __nv_bfloat16 d_W4h[256 * 128];       // BN-folded W4
__device__ float d_B4[256];                      // folded bias conv4

// ---------------- mma / ldmatrix helpers ------------------------------------
__device__ __forceinline__ void mma_bf16(float c[4], unsigned a0, unsigned a1,
                                         unsigned a2, unsigned a3,
                                         unsigned b0, unsigned b1) {
    asm volatile(
        "mma.sync.aligned.m16n8k16.row.col.f32.bf16.bf16.f32 "
        "{%0,%1,%2,%3}, {%4,%5,%6,%7}, {%8,%9}, {%0,%1,%2,%3};"
        : "+f"(c[0]), "+f"(c[1]), "+f"(c[2]), "+f"(c[3])
        : "r"(a0), "r"(a1), "r"(a2), "r"(a3), "r"(b0), "r"(b1));
}
__device__ __forceinline__ unsigned smem_u32(const void* p) {
    return (unsigned)__cvta_generic_to_shared(p);
}
__device__ __forceinline__ void ldsm_x4(unsigned& r0, unsigned& r1, unsigned& r2,
                                        unsigned& r3, unsigned addr) {
    asm volatile("ldmatrix.sync.aligned.m8n8.x4.shared.b16 {%0,%1,%2,%3}, [%4];"
                 : "=r"(r0), "=r"(r1), "=r"(r2), "=r"(r3) : "r"(addr));
}
__device__ __forceinline__ void ldsm_x2t(unsigned& r0, unsigned& r1, unsigned addr) {
    asm volatile("ldmatrix.sync.aligned.m8n8.x2.trans.shared.b16 {%0,%1}, [%2];"
                 : "=r"(r0), "=r"(r1) : "r"(addr));
}
__device__ __forceinline__ unsigned bf2u(float a, float b) {
    __nv_bfloat162 h = __floats2bfloat162_rn(a, b);
    return *(unsigned*)&h;
}

// ---------------------------------------------------------------------------
// prep: fold BN into weights (bf16) and biases (fp32)
// ---------------------------------------------------------------------------
__global__ void __launch_bounds__(256) prep_kernel(
    const float* __restrict__ w1, const float* __restrict__ b1,
    const float* __restrict__ s1, const float* __restrict__ t1,
    const float* __restrict__ m1, const float* __restrict__ v1,
    const float* __restrict__ w2, const float* __restrict__ b2,
    const float* __restrict__ s2, const float* __restrict__ t2,
    const float* __restrict__ m2, const float* __restrict__ v2,
    const float* __restrict__ w3, const float* __restrict__ b3,
    const float* __restrict__ s3, const float* __restrict__ t3,
    const float* __restrict__ m3, const float* __restrict__ v3,
    const float* __restrict__ w4, const float* __restrict__ b4,
    const float* __restrict__ s4, const float* __restrict__ t4,
    const float* __restrict__ m4, const float* __restrict__ v4)
{
    int gid = blockIdx.x * 256 + threadIdx.x;
    int stride = gridDim.x * 256;

    if (gid < 192) {
        int oc = gid;
        float al, bb;
        if (oc < 32) {
            al = s1[oc] * rsqrtf(v1[oc] + EPSV);
            bb = (b1[oc] - m1[oc]) * al + t1[oc];
        } else if (oc < 64) {
            int o = oc - 32;
            al = s2[o] * rsqrtf(v2[o] + EPSV);
            bb = (b2[o] - m2[o]) * al + t2[o];
        } else {
            int o = oc - 64;
            al = s3[o] * rsqrtf(v3[o] + EPSV);
            bb = (b3[o] - m3[o]) * al + t3[o];
        }
        d_Bc[oc] = bb;
    } else if (gid < 448) {
        int oc = gid - 192;
        float al = s4[oc] * rsqrtf(v4[oc] + EPSV);
        d_B4[oc] = (b4[oc] - m4[oc]) * al + t4[oc];
    }

    for (int j = gid; j < 192 * 256; j += stride) {
        int oc = j >> 8, k = j & 255;
        float wv, al;
        if (oc < 32) {
            al = s1[oc] * rsqrtf(v1[oc] + EPSV);
            wv = w1[oc * 256 + k];
        } else if (oc < 64) {
            int o = oc - 32;
            al = s2[o] * rsqrtf(v2[o] + EPSV);
            wv = w2[o * 256 + k];
        } else {
            int o = oc - 64;
            al = s3[o] * rsqrtf(v3[o] + EPSV);
            wv = w3[o * 256 + k];
        }
        d_Wc[j] = __float2bfloat16_rn(wv * al);
    }
    for (int j = gid; j < 256 * 128; j += stride) {
        int oc = j >> 7;
        float al = s4[oc] * rsqrtf(v4[oc] + EPSV);
        d_W4h[j] = __float2bfloat16_rn(w4[j] * al);
    }
}

// ---------------------------------------------------------------------------
// Fused conv1+2+3 via tensor cores (unchanged from R9).
// ---------------------------------------------------------------------------
__global__ void __launch_bounds__(512) conv123_kernel(const float* __restrict__ x)
{
    __shared__ __align__(16) char sm[45056];
    __nv_bfloat16* Xs = (__nv_bfloat16*)sm;             // [64][136]
    __nv_bfloat16* Ws = (__nv_bfloat16*)(sm + 17408);   // [192][72]
    __nv_bfloat16* HP1 = (__nv_bfloat16*)sm;            // [32][64]  (epilogue)
    __nv_bfloat16* HP3 = (__nv_bfloat16*)(sm + 4096);   // [128][64] (epilogue)
    __nv_bfloat16* Gt  = (__nv_bfloat16*)(sm + 20480);  // [128][40] (epilogue)

    const int b = blockIdx.y, r = blockIdx.x, t = threadIdx.x;
    const int lane = t & 31, wid = t >> 5;
    const int g = lane >> 2, t4 = lane & 3;
    const int oc0w = (wid & 3) * 48, m0w = (wid >> 2) * 32;

    const float* xb = x + (size_t)b * 1048576 + (size_t)r * 128;

    float c[3][4][4];
#pragma unroll
    for (int i = 0; i < 3; i++)
#pragma unroll
        for (int j = 0; j < 4; j++)
#pragma unroll
            for (int e = 0; e < 4; e++) c[i][j][e] = 0.f;

    for (int kc = 0; kc < 256; kc += 64) {
        __syncthreads();
#pragma unroll
        for (int j = 0; j < 4; j++) {
            int i = t + j * 512;
            int row = i >> 5, col4 = i & 31;
            float4 v = *(const float4*)(xb + (size_t)(kc + row) * 4096 + col4 * 4);
            uint2 u;
            u.x = bf2u(v.x, v.y);
            u.y = bf2u(v.z, v.w);
            *(uint2*)(Xs + row * 136 + col4 * 4) = u;
        }
#pragma unroll
        for (int j = 0; j < 3; j++) {
            int i = t + j * 512;
            int row = i >> 3, part = i & 7;
            *(uint4*)(Ws + row * 72 + part * 8) =
                *(const uint4*)(d_Wc + row * 256 + kc + part * 8);
        }
        __syncthreads();

#pragma unroll
        for (int ks = 0; ks < 4; ks++) {
            int k0 = ks * 16;
            unsigned a[3][4];
#pragma unroll
            for (int mt = 0; mt < 3; mt++) {
                unsigned addr = smem_u32(Ws + (oc0w + mt * 16 + (lane & 15)) * 72 +
                                         k0 + ((lane >> 4) << 3));
                ldsm_x4(a[mt][0], a[mt][1], a[mt][2], a[mt][3], addr);
            }
#pragma unroll
            for (int nt = 0; nt < 4; nt++) {
                unsigned b0, b1;
                unsigned addr = smem_u32(Xs + (k0 + (lane & 15)) * 136 + m0w + nt * 8);
                ldsm_x2t(b0, b1, addr);
#pragma unroll
                for (int mt = 0; mt < 3; mt++)
                    mma_bf16(c[mt][nt], a[mt][0], a[mt][1], a[mt][2], a[mt][3], b0, b1);
            }
        }
    }
    __syncthreads();

#pragma unroll
    for (int mt = 0; mt < 3; mt++) {
        int ocb = oc0w + mt * 16;
        float bg  = d_Bc[ocb + g];
        float bg8 = d_Bc[ocb + 8 + g];
#pragma unroll
        for (int nt = 0; nt < 4; nt++) {
            int mloc = m0w + nt * 8 + 2 * t4;
            int rh = mloc >> 6, cp = (mloc & 63) >> 1;
            float v0 = fmaxf(c[mt][nt][0] + bg, 0.f);
            float v1 = fmaxf(c[mt][nt][1] + bg, 0.f);
            float v2 = fmaxf(c[mt][nt][2] + bg8, 0.f);
            float v3 = fmaxf(c[mt][nt][3] + bg8, 0.f);
            if (ocb < 32) {
                HP1[(ocb + g) * 64 + rh * 32 + cp]     = __float2bfloat16_rn(fmaxf(v0, v1));
                HP1[(ocb + 8 + g) * 64 + rh * 32 + cp] = __float2bfloat16_rn(fmaxf(v2, v3));
            } else if (ocb < 64) {
                int oc = ocb - 32 + g;
                Gt[mloc * 40 + oc]           = __float2bfloat16_rn(v0);
                Gt[(mloc + 1) * 40 + oc]     = __float2bfloat16_rn(v1);
                Gt[mloc * 40 + oc + 8]       = __float2bfloat16_rn(v2);
                Gt[(mloc + 1) * 40 + oc + 8] = __float2bfloat16_rn(v3);
            } else {
                HP3[(ocb - 64 + g) * 64 + rh * 32 + cp]     = __float2bfloat16_rn(fmaxf(v0, v1));
                HP3[(ocb - 64 + 8 + g) * 64 + rh * 32 + cp] = __float2bfloat16_rn(fmaxf(v2, v3));
            }
        }
    }
    __syncthreads();

    {   // d_Fh: 32 n x 32 oc
        int cp = t >> 4, oc0 = (t & 15) * 2;
        float f0 = __bfloat162float(__hmax(HP1[oc0 * 64 + cp], HP1[oc0 * 64 + 32 + cp]));
        float f1 = __bfloat162float(__hmax(HP1[(oc0 + 1) * 64 + cp], HP1[(oc0 + 1) * 64 + 32 + cp]));
        __nv_bfloat162 h = __floats2bfloat162_rn(f0, f1);
        *(__nv_bfloat162*)(d_Fh + (size_t)b * 32768 + (size_t)(r * 32 + cp) * 32 + oc0) = h;
    }
    {   // d_Hh: 128 c x 32 n
        int cc = t >> 2, q = (t & 3) * 8;
        __nv_bfloat16 out8[8];
#pragma unroll
        for (int jj = 0; jj < 8; jj++)
            out8[jj] = __hmax(HP3[cc * 64 + q + jj], HP3[cc * 64 + 32 + q + jj]);
        *(uint4*)(d_Hh + (size_t)b * 131072 + (size_t)cc * 1024 + r * 32 + q) =
            *(uint4*)out8;
    }
    {   // d_Ght: 128 m x 32 k
        int row = t >> 2, part = t & 3;
        *(uint4*)(d_Ght + (size_t)b * 131072 + (size_t)(r * 128 + row) * 32 + part * 8) =
            *(uint4*)(Gt + row * 40 + part * 8);
    }
}

// ---------------------------------------------------------------------------
// Flash attention v3: m = mma M dim; P passed in registers (no P smem).
// Block: 128 m x 128 c, n-chunks of 64. 8 warps, warp owns 16 m rows, full K.
// Softmax stats fully in registers (shfl within 4-lane group).
// Writes O as bf16 [m][c].
// ---------------------------------------------------------------------------
__global__ void __launch_bounds__(256, 2) attn_kernel()
{
    __shared__ __align__(16) __nv_bfloat16 Gs[128 * 40];  // [m][k]
    __shared__ __align__(16) __nv_bfloat16 Fs[64 * 40];   // [n][k]
    __shared__ __align__(16) __nv_bfloat16 Vs[128 * 72];  // [c][n]

    const int b = blockIdx.y;
    const int m0 = blockIdx.x * 128;
    const int t = threadIdx.x;
    const int lane = t & 31, wid = t >> 5;
    const int g = lane >> 2, t4 = lane & 3;
    const int q = lane & 7, sel = lane >> 3;

    const __nv_bfloat16* gB = d_Ght + (size_t)b * 131072;
    const __nv_bfloat16* fB = d_Fh + (size_t)b * 32768;
    const __nv_bfloat16* hB = d_Hh + (size_t)b * 131072;

    // stage G tile [128][32] once
#pragma unroll
    for (int j = 0; j < 2; j++) {
        int i = t + j * 256;
        int row = i >> 2, part = i & 3;
        *(uint4*)&Gs[row * 40 + part * 8] =
            *(const uint4*)(gB + (size_t)(m0 + row) * 32 + part * 8);
    }
    __syncthreads();

    // loop-invariant A fragments of G (warp's 16 m rows)
    unsigned ag[2][4];
#pragma unroll
    for (int kt = 0; kt < 2; kt++) {
        unsigned addr = smem_u32(Gs + (wid * 16 + (lane & 15)) * 40 +
                                 kt * 16 + ((lane >> 4) << 3));
        ldsm_x4(ag[kt][0], ag[kt][1], ag[kt][2], ag[kt][3], addr);
    }

    float o[16][4];
#pragma unroll
    for (int i = 0; i < 16; i++)
#pragma unroll
        for (int e = 0; e < 4; e++) o[i][e] = 0.f;
    float rm0 = -1e30f, rm1 = -1e30f, rs0 = 0.f, rs1 = 0.f;

    for (int n0 = 0; n0 < 1024; n0 += 64) {
        __syncthreads();
        {   // Fs [64n][32k]
            int row = t >> 2, part = t & 3;
            *(uint4*)&Fs[row * 40 + part * 8] =
                *(const uint4*)(fB + (size_t)(n0 + row) * 32 + part * 8);
        }
        {   // Vs [128c][64n]
            int cpos = t >> 1, nq = (t & 1) * 32;
            const __nv_bfloat16* src = hB + (size_t)cpos * 1024 + n0 + nq;
#pragma unroll
            for (int j2 = 0; j2 < 4; j2++)
                *(uint4*)&Vs[cpos * 72 + nq + j2 * 8] = *(const uint4*)(src + j2 * 8);
        }
        __syncthreads();

        // ---- GEMM1: S[16m][64n] per warp ----
        float sc[8][4];
#pragma unroll
        for (int nt = 0; nt < 8; nt++)
#pragma unroll
            for (int e = 0; e < 4; e++) sc[nt][e] = 0.f;
#pragma unroll
        for (int kt = 0; kt < 2; kt++)
#pragma unroll
            for (int ntp = 0; ntp < 4; ntp++) {
                unsigned b00, b01, b10, b11;
                unsigned addr = smem_u32(Fs + (ntp * 16 + (sel >> 1) * 8 + q) * 40 +
                                         kt * 16 + (sel & 1) * 8);
                ldsm_x4(b00, b01, b10, b11, addr);
                mma_bf16(sc[ntp * 2],     ag[kt][0], ag[kt][1], ag[kt][2], ag[kt][3], b00, b01);
                mma_bf16(sc[ntp * 2 + 1], ag[kt][0], ag[kt][1], ag[kt][2], ag[kt][3], b10, b11);
            }

        // ---- in-register online softmax (rows g, g+8) ----
        float cm0 = -1e30f, cm1 = -1e30f;
#pragma unroll
        for (int nt = 0; nt < 8; nt++) {
            cm0 = fmaxf(cm0, fmaxf(sc[nt][0], sc[nt][1]));
            cm1 = fmaxf(cm1, fmaxf(sc[nt][2], sc[nt][3]));
        }
        cm0 = fmaxf(cm0, __shfl_xor_sync(0xffffffffu, cm0, 1));
        cm0 = fmaxf(cm0, __shfl_xor_sync(0xffffffffu, cm0, 2));
        cm1 = fmaxf(cm1, __shfl_xor_sync(0xffffffffu, cm1, 1));
        cm1 = fmaxf(cm1, __shfl_xor_sync(0xffffffffu, cm1, 2));
        float nm0 = fmaxf(rm0, cm0), nm1 = fmaxf(rm1, cm1);
        float scl0 = __expf(rm0 - nm0), scl1 = __expf(rm1 - nm1);
        rm0 = nm0; rm1 = nm1;
        rs0 *= scl0; rs1 *= scl1;

        unsigned pa[4][4];
        float s0a = 0.f, s1a = 0.f;
#pragma unroll
        for (int kt2 = 0; kt2 < 4; kt2++) {
            float e00 = __expf(sc[2 * kt2][0] - nm0);
            float e01 = __expf(sc[2 * kt2][1] - nm0);
            float e02 = __expf(sc[2 * kt2][2] - nm1);
            float e03 = __expf(sc[2 * kt2][3] - nm1);
            float e10 = __expf(sc[2 * kt2 + 1][0] - nm0);
            float e11 = __expf(sc[2 * kt2 + 1][1] - nm0);
            float e12 = __expf(sc[2 * kt2 + 1][2] - nm1);
            float e13 = __expf(sc[2 * kt2 + 1][3] - nm1);
            pa[kt2][0] = bf2u(e00, e01);
            pa[kt2][1] = bf2u(e02, e03);
            pa[kt2][2] = bf2u(e10, e11);
            pa[kt2][3] = bf2u(e12, e13);
            s0a += e00 + e01 + e10 + e11;
            s1a += e02 + e03 + e12 + e13;
        }
        rs0 += s0a; rs1 += s1a;

        // rescale O accumulators
#pragma unroll
        for (int ct = 0; ct < 16; ct++) {
            o[ct][0] *= scl0; o[ct][1] *= scl0;
            o[ct][2] *= scl1; o[ct][3] *= scl1;
        }

        // ---- GEMM2: O[16m][128c] += P . V^T ----
#pragma unroll
        for (int kt2 = 0; kt2 < 4; kt2++)
#pragma unroll
            for (int cg2 = 0; cg2 < 8; cg2++) {
                unsigned b00, b01, b10, b11;
                unsigned addr = smem_u32(Vs + (cg2 * 16 + (sel >> 1) * 8 + q) * 72 +
                                         kt2 * 16 + (sel & 1) * 8);
                ldsm_x4(b00, b01, b10, b11, addr);
                mma_bf16(o[cg2 * 2],     pa[kt2][0], pa[kt2][1], pa[kt2][2], pa[kt2][3], b00, b01);
                mma_bf16(o[cg2 * 2 + 1], pa[kt2][0], pa[kt2][1], pa[kt2][2], pa[kt2][3], b10, b11);
            }
    }

    // ---- normalize + store bf16 O[m][c] ----
    rs0 += __shfl_xor_sync(0xffffffffu, rs0, 1);
    rs0 += __shfl_xor_sync(0xffffffffu, rs0, 2);
    rs1 += __shfl_xor_sync(0xffffffffu, rs1, 1);
    rs1 += __shfl_xor_sync(0xffffffffu, rs1, 2);
    float inv0 = 1.f / rs0, inv1 = 1.f / rs1;

    __nv_bfloat16* oB = d_Ot + (size_t)b * 524288;
    int row0 = m0 + wid * 16 + g;
#pragma unroll
    for (int ct = 0; ct < 16; ct++) {
        int cc = ct * 8 + 2 * t4;
        *(__nv_bfloat162*)(oB + (size_t)row0 * 128 + cc) =
            __floats2bfloat162_rn(o[ct][0] * inv0, o[ct][1] * inv0);
        *(__nv_bfloat162*)(oB + (size_t)(row0 + 8) * 128 + cc) =
            __floats2bfloat162_rn(o[ct][2] * inv1, o[ct][3] * inv1);
    }
}

// ---------------------------------------------------------------------------
// conv4 via tensor cores, bf16 O^T input: C[128 oc][128 m] per block, K=128.
// out = gamma*(W4'.O + bias4') + x
// ---------------------------------------------------------------------------
__global__ void __launch_bounds__(256) conv4_kernel(
    const float* __restrict__ x, const float* __restrict__ gamma,
    float* __restrict__ out)
{
    __shared__ __align__(16) __nv_bfloat16 Ots[128 * 72];  // [m][c-chunk]
    __shared__ __align__(16) __nv_bfloat16 W4s[128 * 72];  // [oc][c-chunk]

    const int b = blockIdx.z, OC0 = blockIdx.y * 128, pos0 = blockIdx.x * 128;
    const int t = threadIdx.x;
    const int lane = t & 31, wid = t >> 5;
    const int g = lane >> 2, t4 = lane & 3;
    const int q = lane & 7, sel = lane >> 3;
    const int oc0w = (wid & 3) * 32, m0w = (wid >> 2) * 64;

    float c[2][8][4];
#pragma unroll
    for (int i = 0; i < 2; i++)
#pragma unroll
        for (int j = 0; j < 8; j++)
#pragma unroll
            for (int e = 0; e < 4; e++) c[i][j][e] = 0.f;

    for (int kc = 0; kc < 128; kc += 64) {
        __syncthreads();
        {
            int row = t >> 1, cq = (t & 1) * 32;
            const __nv_bfloat16* src =
                d_Ot + ((size_t)b * 4096 + pos0 + row) * 128 + kc + cq;
#pragma unroll
            for (int j = 0; j < 4; j++)
                *(uint4*)&Ots[row * 72 + cq + j * 8] = *(const uint4*)(src + j * 8);
            const __nv_bfloat16* wsrc = d_W4h + (size_t)(OC0 + row) * 128 + kc + cq;
#pragma unroll
            for (int j = 0; j < 4; j++)
                *(uint4*)&W4s[row * 72 + cq + j * 8] = *(const uint4*)(wsrc + j * 8);
        }
        __syncthreads();

#pragma unroll
        for (int ks = 0; ks < 4; ks++) {
            int k0 = ks * 16;
            unsigned a[2][4];
#pragma unroll
            for (int mt = 0; mt < 2; mt++) {
                unsigned addr = smem_u32(W4s + (oc0w + mt * 16 + (lane & 15)) * 72 +
                                         k0 + ((lane >> 4) << 3));
                ldsm_x4(a[mt][0], a[mt][1], a[mt][2], a[mt][3], addr);
            }
#pragma unroll
            for (int mgp = 0; mgp < 4; mgp++) {
                unsigned b00, b01, b10, b11;
                unsigned addr = smem_u32(Ots + (m0w + mgp * 16 + (sel >> 1) * 8 + q) * 72 +
                                         k0 + (sel & 1) * 8);
                ldsm_x4(b00, b01, b10, b11, addr);
                mma_bf16(c[0][mgp * 2],     a[0][0], a[0][1], a[0][2], a[0][3], b00, b01);
                mma_bf16(c[0][mgp * 2 + 1], a[0][0], a[0][1], a[0][2], a[0][3], b10, b11);
                mma_bf16(c[1][mgp * 2],     a[1][0], a[1][1], a[1][2], a[1][3], b00, b01);
                mma_bf16(c[1][mgp * 2 + 1], a[1][0], a[1][1], a[1][2], a[1][3], b10, b11);
            }
        }
    }

    float gm = *gamma;
#pragma unroll
    for (int mt = 0; mt < 2; mt++) {
        int ocA = OC0 + oc0w + mt * 16 + g;
        int ocB = ocA + 8;
        float bA = d_B4[ocA], bB = d_B4[ocB];
        size_t baseA = (size_t)b * 1048576 + (size_t)ocA * 4096 + pos0 + m0w;
        size_t baseB = (size_t)b * 1048576 + (size_t)ocB * 4096 + pos0 + m0w;
#pragma unroll
        for (int nt = 0; nt < 8; nt++) {
            int moff = nt * 8 + 2 * t4;
            float2 xa = *(const float2*)(x + baseA + moff);
            float2 ra;
            ra.x = gm * (c[mt][nt][0] + bA) + xa.x;
            ra.y = gm * (c[mt][nt][1] + bA) + xa.y;
            *(float2*)(out + baseA + moff) = ra;
            float2 xb = *(const float2*)(x + baseB + moff);
            float2 rb;
            rb.x = gm * (c[mt][nt][2] + bB) + xb.x;
            rb.y = gm * (c[mt][nt][3] + bB) + xb.y;
            *(float2*)(out + baseB + moff) = rb;
        }
    }
}

// ---------------------------------------------------------------------------
extern "C" void kernel_launch(void* const* d_in, const int* in_sizes, int n_in,
                              void* d_out, int out_size)
{
    const float* x = (const float*)d_in[0];
    const float* w1 = (const float*)d_in[1];
    const float* b1 = (const float*)d_in[2];
    const float* s1 = (const float*)d_in[3];
    const float* t1 = (const float*)d_in[4];
    const float* m1 = (const float*)d_in[5];
    const float* v1 = (const float*)d_in[6];
    const float* w2 = (const float*)d_in[7];
    const float* b2 = (const float*)d_in[8];
    const float* s2 = (const float*)d_in[9];
    const float* t2 = (const float*)d_in[10];
    const float* m2 = (const float*)d_in[11];
    const float* v2 = (const float*)d_in[12];
    const float* w3 = (const float*)d_in[13];
    const float* b3 = (const float*)d_in[14];
    const float* s3 = (const float*)d_in[15];
    const float* t3 = (const float*)d_in[16];
    const float* m3 = (const float*)d_in[17];
    const float* v3 = (const float*)d_in[18];
    const float* w4 = (const float*)d_in[19];
    const float* b4 = (const float*)d_in[20];
    const float* s4 = (const float*)d_in[21];
    const float* t4 = (const float*)d_in[22];
    const float* m4 = (const float*)d_in[23];
    const float* v4 = (const float*)d_in[24];
    const float* gamma = (const float*)d_in[25];

    prep_kernel<<<64, 256>>>(w1, b1, s1, t1, m1, v1,
                             w2, b2, s2, t2, m2, v2,
                             w3, b3, s3, t3, m3, v3,
                             w4, b4, s4, t4, m4, v4);
    conv123_kernel<<<dim3(32, 8), 512>>>(x);
    attn_kernel<<<dim3(32, 8), 256>>>();
    conv4_kernel<<<dim3(32, 2, 8), 256>>>(x, gamma, (float*)d_out);
}